// round 9
// baseline (speedup 1.0000x reference)
#include <cuda_runtime.h>
#include <cuda_fp16.h>

#define N_NODES 100000
#define N_EDGES 1600000
#define D_IN    480
#define D_OUT   256
#define NEG_SLOPE 0.2f

// ---------------- scratch ----------------
__device__ unsigned g_xl_h[(size_t)N_NODES * (D_OUT / 2)];
__device__ unsigned g_xr_h[(size_t)N_NODES * (D_OUT / 2)];
__device__ int      g_counts[N_NODES];
__device__ int      g_offs[N_NODES];
__device__ int      g_wpos[N_NODES];
__device__ int      g_csrc[N_EDGES];
__device__ int      g_bsum[128];
__device__ int      g_bsum_ex[128];

__device__ __forceinline__ float tf32r(float x) {
    unsigned r;
    asm("cvt.rna.tf32.f32 %0, %1;" : "=r"(r) : "f"(x));
    return __uint_as_float(r);
}
__device__ __forceinline__ unsigned pack_half2(float lo, float hi) {
    unsigned r;
    asm("cvt.rn.f16x2.f32 %0, %1, %2;" : "=r"(r) : "f"(hi), "f"(lo));
    return r;
}
__device__ __forceinline__ float2 h2f2(unsigned u) {
    __half2 h = *reinterpret_cast<__half2*>(&u);
    return __half22float2(h);
}
__device__ __forceinline__ void cvt8(uint4 u, float* x) {
    float2 f;
    f = h2f2(u.x); x[0] = f.x; x[1] = f.y;
    f = h2f2(u.y); x[2] = f.x; x[3] = f.y;
    f = h2f2(u.z); x[4] = f.x; x[5] = f.y;
    f = h2f2(u.w); x[6] = f.x; x[7] = f.y;
}

// ---------------- K0: init ----------------
__global__ void init_kernel() {
    int i = blockIdx.x * blockDim.x + threadIdx.x;
    if (i < N_NODES) g_counts[i] = 0;
}

// ---------------- K2: dst histogram ----------------
__global__ void hist_kernel(const int* __restrict__ ei) {
    int e = blockIdx.x * blockDim.x + threadIdx.x;
    if (e < N_EDGES) atomicAdd(&g_counts[ei[N_EDGES + e]], 1);
}

// ---------------- K1: pipelined dual GEMM via tf32 mma.sync ----------------
#define GBM 128
#define GBN 128
#define GBK 16
#define PADA 20
#define PADB 136
#define NIT (D_IN / GBK)   // 30

__global__ __launch_bounds__(256, 2)
void gemm_tf32_kernel(const float* __restrict__ X,
                      const float* __restrict__ W_l, const float* __restrict__ b_l,
                      const float* __restrict__ W_r, const float* __restrict__ b_r) {
    __shared__ float As[2][GBM * PADA];
    __shared__ float Bs[2][GBK * PADB];

    int tx   = threadIdx.x;
    int lane = tx & 31;
    int wid  = tx >> 5;
    int warp_m = wid & 3;
    int warp_n = wid >> 2;

    int row0 = blockIdx.y * GBM;
    int col0 = blockIdx.x * GBN;

    const float* W; const float* bv; unsigned* Yh;
    int wc = col0;
    if (col0 < D_OUT) { W = W_l; bv = b_l; Yh = g_xl_h; }
    else              { W = W_r; bv = b_r; Yh = g_xr_h; wc = col0 - D_OUT; }

    int am  = (tx >> 2);
    int akq = (tx & 3);
    int bk  = (tx >> 5);
    int bnq = (tx & 31);

    float4 ra[2], rb[2];

    auto loadG = [&](int it) {
#pragma unroll
        for (int i = 0; i < 2; i++) {
            int m  = am + i * 64;
            int gr = row0 + m;
            float4 v = make_float4(0.f, 0.f, 0.f, 0.f);
            if (gr < N_NODES)
                v = *reinterpret_cast<const float4*>(X + (size_t)gr * D_IN + it * GBK + akq * 4);
            ra[i] = v;
        }
#pragma unroll
        for (int i = 0; i < 2; i++) {
            int k = bk + i * 8;
            rb[i] = *reinterpret_cast<const float4*>(W + (size_t)(it * GBK + k) * D_OUT + wc + bnq * 4);
        }
    };
    auto storeS = [&](int buf) {
#pragma unroll
        for (int i = 0; i < 2; i++) {
            int m = am + i * 64;
            float4 v = ra[i];
            v.x = tf32r(v.x); v.y = tf32r(v.y); v.z = tf32r(v.z); v.w = tf32r(v.w);
            *reinterpret_cast<float4*>(&As[buf][m * PADA + akq * 4]) = v;
        }
#pragma unroll
        for (int i = 0; i < 2; i++) {
            int k = bk + i * 8;
            float4 v = rb[i];
            v.x = tf32r(v.x); v.y = tf32r(v.y); v.z = tf32r(v.z); v.w = tf32r(v.w);
            *reinterpret_cast<float4*>(&Bs[buf][k * PADB + bnq * 4]) = v;
        }
    };

    float acc[2][8][4];
#pragma unroll
    for (int mt = 0; mt < 2; mt++)
#pragma unroll
        for (int nt = 0; nt < 8; nt++)
#pragma unroll
            for (int i = 0; i < 4; i++) acc[mt][nt][i] = 0.f;

    loadG(0);
    storeS(0);
    __syncthreads();

    for (int it = 0; it < NIT; it++) {
        int cur = it & 1;
        if (it + 1 < NIT) loadG(it + 1);

#pragma unroll
        for (int ks = 0; ks < 2; ks++) {
            int kk = ks * 8 + (lane & 3);
            unsigned a[2][4];
#pragma unroll
            for (int mt = 0; mt < 2; mt++) {
                int r = warp_m * 32 + mt * 16 + (lane >> 2);
                a[mt][0] = __float_as_uint(As[cur][r * PADA + kk]);
                a[mt][1] = __float_as_uint(As[cur][(r + 8) * PADA + kk]);
                a[mt][2] = __float_as_uint(As[cur][r * PADA + kk + 4]);
                a[mt][3] = __float_as_uint(As[cur][(r + 8) * PADA + kk + 4]);
            }
#pragma unroll
            for (int nt = 0; nt < 8; nt++) {
                int n = warp_n * 64 + nt * 8 + (lane >> 2);
                unsigned b0 = __float_as_uint(Bs[cur][kk * PADB + n]);
                unsigned b1 = __float_as_uint(Bs[cur][(kk + 4) * PADB + n]);
#pragma unroll
                for (int mt = 0; mt < 2; mt++) {
                    asm volatile(
                        "mma.sync.aligned.m16n8k8.row.col.f32.tf32.tf32.f32 "
                        "{%0,%1,%2,%3}, {%4,%5,%6,%7}, {%8,%9}, {%0,%1,%2,%3};"
                        : "+f"(acc[mt][nt][0]), "+f"(acc[mt][nt][1]),
                          "+f"(acc[mt][nt][2]), "+f"(acc[mt][nt][3])
                        : "r"(a[mt][0]), "r"(a[mt][1]), "r"(a[mt][2]), "r"(a[mt][3]),
                          "r"(b0), "r"(b1));
                }
            }
        }

        if (it + 1 < NIT) storeS((it + 1) & 1);
        __syncthreads();
    }

#pragma unroll
    for (int mt = 0; mt < 2; mt++) {
        int r = row0 + warp_m * 32 + mt * 16 + (lane >> 2);
#pragma unroll
        for (int nt = 0; nt < 8; nt++) {
            int c = wc + warp_n * 64 + nt * 8 + (lane & 3) * 2;
            if (r < N_NODES) {
                Yh[(size_t)r * (D_OUT / 2) + (c >> 1)] =
                    pack_half2(acc[mt][nt][0] + bv[c], acc[mt][nt][1] + bv[c + 1]);
            }
            if (r + 8 < N_NODES) {
                Yh[(size_t)(r + 8) * (D_OUT / 2) + (c >> 1)] =
                    pack_half2(acc[mt][nt][2] + bv[c], acc[mt][nt][3] + bv[c + 1]);
            }
        }
    }
}

// ---------------- K3: exclusive scan ----------------
#define SCAN_CH 1024
#define SCAN_NBLK ((N_NODES + SCAN_CH - 1) / SCAN_CH)   // 98

__global__ void scan1_kernel() {
    __shared__ int sh[SCAN_CH];
    int t = threadIdx.x;
    int g = blockIdx.x * SCAN_CH + t;
    int v = (g < N_NODES) ? g_counts[g] : 0;
    sh[t] = v;
    __syncthreads();
    for (int o = 1; o < SCAN_CH; o <<= 1) {
        int x = (t >= o) ? sh[t - o] : 0;
        __syncthreads();
        sh[t] += x;
        __syncthreads();
    }
    if (g < N_NODES) g_offs[g] = sh[t] - v;
    if (t == SCAN_CH - 1) g_bsum[blockIdx.x] = sh[t];
}

__global__ void scan2_kernel() {
    __shared__ int sh[128];
    int t = threadIdx.x;
    int v = (t < SCAN_NBLK) ? g_bsum[t] : 0;
    sh[t] = v;
    __syncthreads();
    for (int o = 1; o < 128; o <<= 1) {
        int x = (t >= o) ? sh[t - o] : 0;
        __syncthreads();
        sh[t] += x;
        __syncthreads();
    }
    if (t < SCAN_NBLK) g_bsum_ex[t] = sh[t] - v;
}

__global__ void scan3_kernel() {
    int g = blockIdx.x * SCAN_CH + threadIdx.x;
    if (g < N_NODES) {
        int v = g_offs[g] + g_bsum_ex[blockIdx.x];
        g_offs[g] = v;
        g_wpos[g] = v;
    }
}

// ---------------- K4: CSR scatter of src ids ----------------
__global__ void scatter_kernel(const int* __restrict__ ei) {
    int e = blockIdx.x * blockDim.x + threadIdx.x;
    if (e >= N_EDGES) return;
    int s = __ldg(&ei[e]);
    int d = __ldg(&ei[N_EDGES + e]);
    int pos = atomicAdd(&g_wpos[d], 1);
    g_csrc[pos] = s;
}

// ---------------- K5: fused logits+softmax+aggregate, 4-edge groups ----------------
__global__ __launch_bounds__(256)
void fused_node_kernel(const float* __restrict__ att,
                       const float* __restrict__ bias,
                       float* __restrict__ out) {
    int node = blockIdx.x * 8 + (threadIdx.x >> 5);
    if (node >= N_NODES) return;
    int lane = threadIdx.x & 31;
    int beg = g_offs[node];
    int cnt = g_counts[node];

    float xr[8], at[8];
    cvt8(*reinterpret_cast<const uint4*>(g_xr_h + (size_t)node * 128 + lane * 4), xr);
    { const float4* atp = reinterpret_cast<const float4*>(att);
      float4 a0 = atp[lane * 2], a1 = atp[lane * 2 + 1];
      at[0] = a0.x; at[1] = a0.y; at[2] = a0.z; at[3] = a0.w;
      at[4] = a1.x; at[5] = a1.y; at[6] = a1.z; at[7] = a1.w; }

    float acc[8];
#pragma unroll
    for (int i = 0; i < 8; i++) acc[i] = 0.f;
    float denom = 0.f;

    for (int base = 0; base < cnt; base += 32) {
        int nb = min(32, cnt - base);
        int s_reg = (lane < nb) ? g_csrc[beg + base + lane] : 0;

        for (int jj = 0; jj < nb; jj += 4) {
            // shfl indices jj..jj+3 <= 31 always (jj < nb <= 32, step 4)
            int s0 = __shfl_sync(0xffffffffu, s_reg, jj);
            int s1 = __shfl_sync(0xffffffffu, s_reg, jj + 1);
            int s2 = __shfl_sync(0xffffffffu, s_reg, jj + 2);
            int s3 = __shfl_sync(0xffffffffu, s_reg, jj + 3);

            // 4 independent gathers (MLP=4); invalid slots load node 0 (safe), weight masked later
            uint4 u0 = *reinterpret_cast<const uint4*>(g_xl_h + (size_t)s0 * 128 + lane * 4);
            uint4 u1 = *reinterpret_cast<const uint4*>(g_xl_h + (size_t)s1 * 128 + lane * 4);
            uint4 u2 = *reinterpret_cast<const uint4*>(g_xl_h + (size_t)s2 * 128 + lane * 4);
            uint4 u3 = *reinterpret_cast<const uint4*>(g_xl_h + (size_t)s3 * 128 + lane * 4);

            float x0[8], x1[8], x2[8], x3[8];
            cvt8(u0, x0); cvt8(u1, x1); cvt8(u2, x2); cvt8(u3, x3);

            float p0 = 0.f, p1 = 0.f, p2 = 0.f, p3 = 0.f;
#pragma unroll
            for (int i = 0; i < 8; i++) {
                float h0 = x0[i] + xr[i]; h0 = h0 > 0.f ? h0 : NEG_SLOPE * h0;
                float h1 = x1[i] + xr[i]; h1 = h1 > 0.f ? h1 : NEG_SLOPE * h1;
                float h2 = x2[i] + xr[i]; h2 = h2 > 0.f ? h2 : NEG_SLOPE * h2;
                float h3 = x3[i] + xr[i]; h3 = h3 > 0.f ? h3 : NEG_SLOPE * h3;
                p0 = fmaf(at[i], h0, p0);
                p1 = fmaf(at[i], h1, p1);
                p2 = fmaf(at[i], h2, p2);
                p3 = fmaf(at[i], h3, p3);
            }
            // 4 parallel butterfly reductions (ILP hides shfl latency)
#pragma unroll
            for (int o = 16; o > 0; o >>= 1) {
                p0 += __shfl_xor_sync(0xffffffffu, p0, o);
                p1 += __shfl_xor_sync(0xffffffffu, p1, o);
                p2 += __shfl_xor_sync(0xffffffffu, p2, o);
                p3 += __shfl_xor_sync(0xffffffffu, p3, o);
            }
            float w0 = (jj + 0 < nb) ? __expf(p0) : 0.f;
            float w1 = (jj + 1 < nb) ? __expf(p1) : 0.f;
            float w2 = (jj + 2 < nb) ? __expf(p2) : 0.f;
            float w3 = (jj + 3 < nb) ? __expf(p3) : 0.f;
            denom += (w0 + w1) + (w2 + w3);
#pragma unroll
            for (int i = 0; i < 8; i++) {
                float t0 = fmaf(w0, x0[i], acc[i]);
                float t1 = fmaf(w1, x1[i], t0);
                float t2 = fmaf(w2, x2[i], t1);
                acc[i]   = fmaf(w3, x3[i], t2);
            }
        }
    }

    float rd = 1.f / (denom + 1e-16f);
    const float4* bi = reinterpret_cast<const float4*>(bias);
    float4 bb0 = bi[lane * 2], bb1 = bi[lane * 2 + 1];
    float4 o0 = make_float4(fmaf(acc[0], rd, bb0.x), fmaf(acc[1], rd, bb0.y),
                            fmaf(acc[2], rd, bb0.z), fmaf(acc[3], rd, bb0.w));
    float4 o1 = make_float4(fmaf(acc[4], rd, bb1.x), fmaf(acc[5], rd, bb1.y),
                            fmaf(acc[6], rd, bb1.z), fmaf(acc[7], rd, bb1.w));
    float4* op = reinterpret_cast<float4*>(out + (size_t)node * D_OUT + lane * 8);
    op[0] = o0;
    op[1] = o1;
}

// ---------------- launch ----------------
extern "C" void kernel_launch(void* const* d_in, const int* in_sizes, int n_in,
                              void* d_out, int out_size) {
    const float* x    = (const float*)d_in[0];
    const int*   ei   = (const int*)d_in[1];
    const float* W_l  = (const float*)d_in[2];
    const float* b_l  = (const float*)d_in[3];
    const float* W_r  = (const float*)d_in[4];
    const float* b_r  = (const float*)d_in[5];
    const float* att  = (const float*)d_in[6];
    const float* bias = (const float*)d_in[7];
    float* out = (float*)d_out;

    init_kernel<<<(N_NODES + 255) / 256, 256>>>();
    hist_kernel<<<(N_EDGES + 255) / 256, 256>>>(ei);

    dim3 ggrid(2 * D_OUT / GBN, (N_NODES + GBM - 1) / GBM);   // (4, 782)
    gemm_tf32_kernel<<<ggrid, 256>>>(x, W_l, b_l, W_r, b_r);

    scan1_kernel<<<SCAN_NBLK, SCAN_CH>>>();
    scan2_kernel<<<1, 128>>>();
    scan3_kernel<<<SCAN_NBLK, SCAN_CH>>>();

    scatter_kernel<<<(N_EDGES + 255) / 256, 256>>>(ei);

    fused_node_kernel<<<(N_NODES + 7) / 8, 256>>>(att, bias, out);
}

// round 10
// speedup vs baseline: 1.5660x; 1.5660x over previous
#include <cuda_runtime.h>
#include <cuda_fp16.h>

#define N_NODES 100000
#define N_EDGES 1600000
#define D_IN    480
#define D_OUT   256
#define NEG_SLOPE 0.2f

// ---------------- scratch ----------------
__device__ unsigned g_xl_h[(size_t)N_NODES * (D_OUT / 2)];
__device__ unsigned g_xr_h[(size_t)N_NODES * (D_OUT / 2)];
__device__ int      g_counts[N_NODES];
__device__ int      g_offs[N_NODES];
__device__ int      g_wpos[N_NODES];
__device__ int      g_csrc[N_EDGES];
__device__ int      g_bsum[128];
__device__ int      g_bsum_ex[128];

__device__ __forceinline__ float tf32r(float x) {
    unsigned r;
    asm("cvt.rna.tf32.f32 %0, %1;" : "=r"(r) : "f"(x));
    return __uint_as_float(r);
}
__device__ __forceinline__ unsigned pack_half2(float lo, float hi) {
    unsigned r;
    asm("cvt.rn.f16x2.f32 %0, %1, %2;" : "=r"(r) : "f"(hi), "f"(lo));
    return r;
}
__device__ __forceinline__ float2 h2f2(unsigned u) {
    __half2 h = *reinterpret_cast<__half2*>(&u);
    return __half22float2(h);
}
__device__ __forceinline__ void cvt8(uint4 u, float* x) {
    float2 f;
    f = h2f2(u.x); x[0] = f.x; x[1] = f.y;
    f = h2f2(u.y); x[2] = f.x; x[3] = f.y;
    f = h2f2(u.z); x[4] = f.x; x[5] = f.y;
    f = h2f2(u.w); x[6] = f.x; x[7] = f.y;
}

// ---------------- K0: init ----------------
__global__ void init_kernel() {
    int i = blockIdx.x * blockDim.x + threadIdx.x;
    if (i < N_NODES) g_counts[i] = 0;
}

// ---------------- K2: dst histogram ----------------
__global__ void hist_kernel(const int* __restrict__ ei) {
    int e = blockIdx.x * blockDim.x + threadIdx.x;
    if (e < N_EDGES) atomicAdd(&g_counts[ei[N_EDGES + e]], 1);
}

// ---------------- K1: pipelined dual GEMM via tf32 mma.sync ----------------
#define GBM 128
#define GBN 128
#define GBK 16
#define PADA 20
#define PADB 136
#define NIT (D_IN / GBK)   // 30

__global__ __launch_bounds__(256, 2)
void gemm_tf32_kernel(const float* __restrict__ X,
                      const float* __restrict__ W_l, const float* __restrict__ b_l,
                      const float* __restrict__ W_r, const float* __restrict__ b_r) {
    __shared__ float As[2][GBM * PADA];
    __shared__ float Bs[2][GBK * PADB];

    int tx   = threadIdx.x;
    int lane = tx & 31;
    int wid  = tx >> 5;
    int warp_m = wid & 3;
    int warp_n = wid >> 2;

    int row0 = blockIdx.y * GBM;
    int col0 = blockIdx.x * GBN;

    const float* W; const float* bv; unsigned* Yh;
    int wc = col0;
    if (col0 < D_OUT) { W = W_l; bv = b_l; Yh = g_xl_h; }
    else              { W = W_r; bv = b_r; Yh = g_xr_h; wc = col0 - D_OUT; }

    int am  = (tx >> 2);
    int akq = (tx & 3);
    int bk  = (tx >> 5);
    int bnq = (tx & 31);

    float4 ra[2], rb[2];

    auto loadG = [&](int it) {
#pragma unroll
        for (int i = 0; i < 2; i++) {
            int m  = am + i * 64;
            int gr = row0 + m;
            float4 v = make_float4(0.f, 0.f, 0.f, 0.f);
            if (gr < N_NODES)
                v = *reinterpret_cast<const float4*>(X + (size_t)gr * D_IN + it * GBK + akq * 4);
            ra[i] = v;
        }
#pragma unroll
        for (int i = 0; i < 2; i++) {
            int k = bk + i * 8;
            rb[i] = *reinterpret_cast<const float4*>(W + (size_t)(it * GBK + k) * D_OUT + wc + bnq * 4);
        }
    };
    auto storeS = [&](int buf) {
#pragma unroll
        for (int i = 0; i < 2; i++) {
            int m = am + i * 64;
            float4 v = ra[i];
            v.x = tf32r(v.x); v.y = tf32r(v.y); v.z = tf32r(v.z); v.w = tf32r(v.w);
            *reinterpret_cast<float4*>(&As[buf][m * PADA + akq * 4]) = v;
        }
#pragma unroll
        for (int i = 0; i < 2; i++) {
            int k = bk + i * 8;
            float4 v = rb[i];
            v.x = tf32r(v.x); v.y = tf32r(v.y); v.z = tf32r(v.z); v.w = tf32r(v.w);
            *reinterpret_cast<float4*>(&Bs[buf][k * PADB + bnq * 4]) = v;
        }
    };

    float acc[2][8][4];
#pragma unroll
    for (int mt = 0; mt < 2; mt++)
#pragma unroll
        for (int nt = 0; nt < 8; nt++)
#pragma unroll
            for (int i = 0; i < 4; i++) acc[mt][nt][i] = 0.f;

    loadG(0);
    storeS(0);
    __syncthreads();

    for (int it = 0; it < NIT; it++) {
        int cur = it & 1;
        if (it + 1 < NIT) loadG(it + 1);

#pragma unroll
        for (int ks = 0; ks < 2; ks++) {
            int kk = ks * 8 + (lane & 3);
            unsigned a[2][4];
#pragma unroll
            for (int mt = 0; mt < 2; mt++) {
                int r = warp_m * 32 + mt * 16 + (lane >> 2);
                a[mt][0] = __float_as_uint(As[cur][r * PADA + kk]);
                a[mt][1] = __float_as_uint(As[cur][(r + 8) * PADA + kk]);
                a[mt][2] = __float_as_uint(As[cur][r * PADA + kk + 4]);
                a[mt][3] = __float_as_uint(As[cur][(r + 8) * PADA + kk + 4]);
            }
#pragma unroll
            for (int nt = 0; nt < 8; nt++) {
                int n = warp_n * 64 + nt * 8 + (lane >> 2);
                unsigned b0 = __float_as_uint(Bs[cur][kk * PADB + n]);
                unsigned b1 = __float_as_uint(Bs[cur][(kk + 4) * PADB + n]);
#pragma unroll
                for (int mt = 0; mt < 2; mt++) {
                    asm volatile(
                        "mma.sync.aligned.m16n8k8.row.col.f32.tf32.tf32.f32 "
                        "{%0,%1,%2,%3}, {%4,%5,%6,%7}, {%8,%9}, {%0,%1,%2,%3};"
                        : "+f"(acc[mt][nt][0]), "+f"(acc[mt][nt][1]),
                          "+f"(acc[mt][nt][2]), "+f"(acc[mt][nt][3])
                        : "r"(a[mt][0]), "r"(a[mt][1]), "r"(a[mt][2]), "r"(a[mt][3]),
                          "r"(b0), "r"(b1));
                }
            }
        }

        if (it + 1 < NIT) storeS((it + 1) & 1);
        __syncthreads();
    }

#pragma unroll
    for (int mt = 0; mt < 2; mt++) {
        int r = row0 + warp_m * 32 + mt * 16 + (lane >> 2);
#pragma unroll
        for (int nt = 0; nt < 8; nt++) {
            int c = wc + warp_n * 64 + nt * 8 + (lane & 3) * 2;
            if (r < N_NODES) {
                Yh[(size_t)r * (D_OUT / 2) + (c >> 1)] =
                    pack_half2(acc[mt][nt][0] + bv[c], acc[mt][nt][1] + bv[c + 1]);
            }
            if (r + 8 < N_NODES) {
                Yh[(size_t)(r + 8) * (D_OUT / 2) + (c >> 1)] =
                    pack_half2(acc[mt][nt][2] + bv[c], acc[mt][nt][3] + bv[c + 1]);
            }
        }
    }
}

// ---------------- K3: exclusive scan ----------------
#define SCAN_CH 1024
#define SCAN_NBLK ((N_NODES + SCAN_CH - 1) / SCAN_CH)   // 98

__global__ void scan1_kernel() {
    __shared__ int sh[SCAN_CH];
    int t = threadIdx.x;
    int g = blockIdx.x * SCAN_CH + t;
    int v = (g < N_NODES) ? g_counts[g] : 0;
    sh[t] = v;
    __syncthreads();
    for (int o = 1; o < SCAN_CH; o <<= 1) {
        int x = (t >= o) ? sh[t - o] : 0;
        __syncthreads();
        sh[t] += x;
        __syncthreads();
    }
    if (g < N_NODES) g_offs[g] = sh[t] - v;
    if (t == SCAN_CH - 1) g_bsum[blockIdx.x] = sh[t];
}

__global__ void scan2_kernel() {
    __shared__ int sh[128];
    int t = threadIdx.x;
    int v = (t < SCAN_NBLK) ? g_bsum[t] : 0;
    sh[t] = v;
    __syncthreads();
    for (int o = 1; o < 128; o <<= 1) {
        int x = (t >= o) ? sh[t - o] : 0;
        __syncthreads();
        sh[t] += x;
        __syncthreads();
    }
    if (t < SCAN_NBLK) g_bsum_ex[t] = sh[t] - v;
}

__global__ void scan3_kernel() {
    int g = blockIdx.x * SCAN_CH + threadIdx.x;
    if (g < N_NODES) {
        int v = g_offs[g] + g_bsum_ex[blockIdx.x];
        g_offs[g] = v;
        g_wpos[g] = v;
    }
}

// ---------------- K4: CSR scatter of src ids ----------------
__global__ void scatter_kernel(const int* __restrict__ ei) {
    int e = blockIdx.x * blockDim.x + threadIdx.x;
    if (e >= N_EDGES) return;
    int s = __ldg(&ei[e]);
    int d = __ldg(&ei[N_EDGES + e]);
    int pos = atomicAdd(&g_wpos[d], 1);
    g_csrc[pos] = s;
}

// ---------------- K5: fused logits+softmax+aggregate, 2-edge + prefetch ----------------
__global__ __launch_bounds__(256)
void fused_node_kernel(const float* __restrict__ att,
                       const float* __restrict__ bias,
                       float* __restrict__ out) {
    int node = blockIdx.x * 8 + (threadIdx.x >> 5);
    if (node >= N_NODES) return;
    int lane = threadIdx.x & 31;
    int beg = g_offs[node];
    int cnt = g_counts[node];

    float xr[8], at[8];
    cvt8(*reinterpret_cast<const uint4*>(g_xr_h + (size_t)node * 128 + lane * 4), xr);
    { const float4* atp = reinterpret_cast<const float4*>(att);
      float4 a0 = atp[lane * 2], a1 = atp[lane * 2 + 1];
      at[0] = a0.x; at[1] = a0.y; at[2] = a0.z; at[3] = a0.w;
      at[4] = a1.x; at[5] = a1.y; at[6] = a1.z; at[7] = a1.w; }

    float acc[8];
#pragma unroll
    for (int i = 0; i < 8; i++) acc[i] = 0.f;
    float denom = 0.f;

    const unsigned* xlh = g_xl_h;
    int laneoff = lane * 4;

    // prologue: load pair 0 (uniform broadcast loads of src ids; L1-resident)
    uint4 uA = make_uint4(0, 0, 0, 0), uB = make_uint4(0, 0, 0, 0);
    if (cnt > 0) {
        int sA = g_csrc[beg];
        int sB = (cnt > 1) ? g_csrc[beg + 1] : 0;
        uA = *reinterpret_cast<const uint4*>(xlh + (size_t)sA * 128 + laneoff);
        uB = *reinterpret_cast<const uint4*>(xlh + (size_t)sB * 128 + laneoff);
    }

    for (int j = 0; j < cnt; j += 2) {
        // prefetch pair j+2 BEFORE the long reduce chain of pair j
        uint4 uA2 = make_uint4(0, 0, 0, 0), uB2 = make_uint4(0, 0, 0, 0);
        if (j + 2 < cnt) {
            int sA2 = g_csrc[beg + j + 2];
            int sB2 = (j + 3 < cnt) ? g_csrc[beg + j + 3] : 0;
            uA2 = *reinterpret_cast<const uint4*>(xlh + (size_t)sA2 * 128 + laneoff);
            uB2 = *reinterpret_cast<const uint4*>(xlh + (size_t)sB2 * 128 + laneoff);
        }

        float x0[8], x1[8];
        cvt8(uA, x0); cvt8(uB, x1);

        float p0 = 0.f, p1 = 0.f;
#pragma unroll
        for (int i = 0; i < 8; i++) {
            float h0 = x0[i] + xr[i]; h0 = h0 > 0.f ? h0 : NEG_SLOPE * h0;
            float h1 = x1[i] + xr[i]; h1 = h1 > 0.f ? h1 : NEG_SLOPE * h1;
            p0 = fmaf(at[i], h0, p0);
            p1 = fmaf(at[i], h1, p1);
        }
#pragma unroll
        for (int o = 16; o > 0; o >>= 1) {
            p0 += __shfl_xor_sync(0xffffffffu, p0, o);
            p1 += __shfl_xor_sync(0xffffffffu, p1, o);
        }
        float w0 = __expf(p0);
        float w1 = (j + 1 < cnt) ? __expf(p1) : 0.f;
        denom += w0 + w1;
#pragma unroll
        for (int i = 0; i < 8; i++) {
            float t = fmaf(w0, x0[i], acc[i]);
            acc[i]  = fmaf(w1, x1[i], t);
        }

        uA = uA2; uB = uB2;
    }

    float rd = 1.f / (denom + 1e-16f);
    const float4* bi = reinterpret_cast<const float4*>(bias);
    float4 bb0 = bi[lane * 2], bb1 = bi[lane * 2 + 1];
    float4 o0 = make_float4(fmaf(acc[0], rd, bb0.x), fmaf(acc[1], rd, bb0.y),
                            fmaf(acc[2], rd, bb0.z), fmaf(acc[3], rd, bb0.w));
    float4 o1 = make_float4(fmaf(acc[4], rd, bb1.x), fmaf(acc[5], rd, bb1.y),
                            fmaf(acc[6], rd, bb1.z), fmaf(acc[7], rd, bb1.w));
    float4* op = reinterpret_cast<float4*>(out + (size_t)node * D_OUT + lane * 8);
    op[0] = o0;
    op[1] = o1;
}

// ---------------- launch ----------------
extern "C" void kernel_launch(void* const* d_in, const int* in_sizes, int n_in,
                              void* d_out, int out_size) {
    const float* x    = (const float*)d_in[0];
    const int*   ei   = (const int*)d_in[1];
    const float* W_l  = (const float*)d_in[2];
    const float* b_l  = (const float*)d_in[3];
    const float* W_r  = (const float*)d_in[4];
    const float* b_r  = (const float*)d_in[5];
    const float* att  = (const float*)d_in[6];
    const float* bias = (const float*)d_in[7];
    float* out = (float*)d_out;

    init_kernel<<<(N_NODES + 255) / 256, 256>>>();
    hist_kernel<<<(N_EDGES + 255) / 256, 256>>>(ei);

    dim3 ggrid(2 * D_OUT / GBN, (N_NODES + GBM - 1) / GBM);   // (4, 782)
    gemm_tf32_kernel<<<ggrid, 256>>>(x, W_l, b_l, W_r, b_r);

    scan1_kernel<<<SCAN_NBLK, SCAN_CH>>>();
    scan2_kernel<<<1, 128>>>();
    scan3_kernel<<<SCAN_NBLK, SCAN_CH>>>();

    scatter_kernel<<<(N_EDGES + 255) / 256, 256>>>(ei);

    fused_node_kernel<<<(N_NODES + 7) / 8, 256>>>(att, bias, out);
}

// round 11
// speedup vs baseline: 1.6653x; 1.0634x over previous
#include <cuda_runtime.h>
#include <cuda_fp16.h>

#define N_NODES 100000
#define N_EDGES 1600000
#define D_IN    480
#define D_OUT   256
#define NEG_SLOPE 0.2f

// ---------------- scratch ----------------
__device__ unsigned g_xl_h[(size_t)N_NODES * (D_OUT / 2)];
__device__ unsigned g_xr_h[(size_t)N_NODES * (D_OUT / 2)];
__device__ int      g_counts[N_NODES];
__device__ int      g_offs[N_NODES];
__device__ int      g_wpos[N_NODES];
__device__ int      g_csrc[N_EDGES];
__device__ int      g_bsum[128];
__device__ int      g_bsum_ex[128];

__device__ __forceinline__ float tf32r(float x) {
    unsigned r;
    asm("cvt.rna.tf32.f32 %0, %1;" : "=r"(r) : "f"(x));
    return __uint_as_float(r);
}
__device__ __forceinline__ unsigned pack_half2(float lo, float hi) {
    unsigned r;
    asm("cvt.rn.f16x2.f32 %0, %1, %2;" : "=r"(r) : "f"(hi), "f"(lo));
    return r;
}
__device__ __forceinline__ float2 h2f2(unsigned u) {
    __half2 h = *reinterpret_cast<__half2*>(&u);
    return __half22float2(h);
}
__device__ __forceinline__ void cvt8(uint4 u, float* x) {
    float2 f;
    f = h2f2(u.x); x[0] = f.x; x[1] = f.y;
    f = h2f2(u.y); x[2] = f.x; x[3] = f.y;
    f = h2f2(u.z); x[4] = f.x; x[5] = f.y;
    f = h2f2(u.w); x[6] = f.x; x[7] = f.y;
}

// ---------------- K0: init ----------------
__global__ void init_kernel() {
    int i = blockIdx.x * blockDim.x + threadIdx.x;
    if (i < N_NODES) g_counts[i] = 0;
}

// ---------------- K2: dst histogram ----------------
__global__ void hist_kernel(const int* __restrict__ ei) {
    int e = blockIdx.x * blockDim.x + threadIdx.x;
    if (e < N_EDGES) atomicAdd(&g_counts[ei[N_EDGES + e]], 1);
}

// ---------------- K1: pipelined dual GEMM via tf32 mma.sync ----------------
#define GBM 128
#define GBN 128
#define GBK 16
#define PADA 20
#define PADB 136
#define NIT (D_IN / GBK)   // 30

__global__ __launch_bounds__(256, 2)
void gemm_tf32_kernel(const float* __restrict__ X,
                      const float* __restrict__ W_l, const float* __restrict__ b_l,
                      const float* __restrict__ W_r, const float* __restrict__ b_r) {
    __shared__ float As[2][GBM * PADA];
    __shared__ float Bs[2][GBK * PADB];

    int tx   = threadIdx.x;
    int lane = tx & 31;
    int wid  = tx >> 5;
    int warp_m = wid & 3;
    int warp_n = wid >> 2;

    int row0 = blockIdx.y * GBM;
    int col0 = blockIdx.x * GBN;

    const float* W; const float* bv; unsigned* Yh;
    int wc = col0;
    if (col0 < D_OUT) { W = W_l; bv = b_l; Yh = g_xl_h; }
    else              { W = W_r; bv = b_r; Yh = g_xr_h; wc = col0 - D_OUT; }

    int am  = (tx >> 2);
    int akq = (tx & 3);
    int bk  = (tx >> 5);
    int bnq = (tx & 31);

    float4 ra[2], rb[2];

    auto loadG = [&](int it) {
#pragma unroll
        for (int i = 0; i < 2; i++) {
            int m  = am + i * 64;
            int gr = row0 + m;
            float4 v = make_float4(0.f, 0.f, 0.f, 0.f);
            if (gr < N_NODES)
                v = *reinterpret_cast<const float4*>(X + (size_t)gr * D_IN + it * GBK + akq * 4);
            ra[i] = v;
        }
#pragma unroll
        for (int i = 0; i < 2; i++) {
            int k = bk + i * 8;
            rb[i] = *reinterpret_cast<const float4*>(W + (size_t)(it * GBK + k) * D_OUT + wc + bnq * 4);
        }
    };
    auto storeS = [&](int buf) {
#pragma unroll
        for (int i = 0; i < 2; i++) {
            int m = am + i * 64;
            float4 v = ra[i];
            v.x = tf32r(v.x); v.y = tf32r(v.y); v.z = tf32r(v.z); v.w = tf32r(v.w);
            *reinterpret_cast<float4*>(&As[buf][m * PADA + akq * 4]) = v;
        }
#pragma unroll
        for (int i = 0; i < 2; i++) {
            int k = bk + i * 8;
            float4 v = rb[i];
            v.x = tf32r(v.x); v.y = tf32r(v.y); v.z = tf32r(v.z); v.w = tf32r(v.w);
            *reinterpret_cast<float4*>(&Bs[buf][k * PADB + bnq * 4]) = v;
        }
    };

    float acc[2][8][4];
#pragma unroll
    for (int mt = 0; mt < 2; mt++)
#pragma unroll
        for (int nt = 0; nt < 8; nt++)
#pragma unroll
            for (int i = 0; i < 4; i++) acc[mt][nt][i] = 0.f;

    loadG(0);
    storeS(0);
    __syncthreads();

    for (int it = 0; it < NIT; it++) {
        int cur = it & 1;
        if (it + 1 < NIT) loadG(it + 1);

#pragma unroll
        for (int ks = 0; ks < 2; ks++) {
            int kk = ks * 8 + (lane & 3);
            unsigned a[2][4];
#pragma unroll
            for (int mt = 0; mt < 2; mt++) {
                int r = warp_m * 32 + mt * 16 + (lane >> 2);
                a[mt][0] = __float_as_uint(As[cur][r * PADA + kk]);
                a[mt][1] = __float_as_uint(As[cur][(r + 8) * PADA + kk]);
                a[mt][2] = __float_as_uint(As[cur][r * PADA + kk + 4]);
                a[mt][3] = __float_as_uint(As[cur][(r + 8) * PADA + kk + 4]);
            }
#pragma unroll
            for (int nt = 0; nt < 8; nt++) {
                int n = warp_n * 64 + nt * 8 + (lane >> 2);
                unsigned b0 = __float_as_uint(Bs[cur][kk * PADB + n]);
                unsigned b1 = __float_as_uint(Bs[cur][(kk + 4) * PADB + n]);
#pragma unroll
                for (int mt = 0; mt < 2; mt++) {
                    asm volatile(
                        "mma.sync.aligned.m16n8k8.row.col.f32.tf32.tf32.f32 "
                        "{%0,%1,%2,%3}, {%4,%5,%6,%7}, {%8,%9}, {%0,%1,%2,%3};"
                        : "+f"(acc[mt][nt][0]), "+f"(acc[mt][nt][1]),
                          "+f"(acc[mt][nt][2]), "+f"(acc[mt][nt][3])
                        : "r"(a[mt][0]), "r"(a[mt][1]), "r"(a[mt][2]), "r"(a[mt][3]),
                          "r"(b0), "r"(b1));
                }
            }
        }

        if (it + 1 < NIT) storeS((it + 1) & 1);
        __syncthreads();
    }

#pragma unroll
    for (int mt = 0; mt < 2; mt++) {
        int r = row0 + warp_m * 32 + mt * 16 + (lane >> 2);
#pragma unroll
        for (int nt = 0; nt < 8; nt++) {
            int c = wc + warp_n * 64 + nt * 8 + (lane & 3) * 2;
            if (r < N_NODES) {
                Yh[(size_t)r * (D_OUT / 2) + (c >> 1)] =
                    pack_half2(acc[mt][nt][0] + bv[c], acc[mt][nt][1] + bv[c + 1]);
            }
            if (r + 8 < N_NODES) {
                Yh[(size_t)(r + 8) * (D_OUT / 2) + (c >> 1)] =
                    pack_half2(acc[mt][nt][2] + bv[c], acc[mt][nt][3] + bv[c + 1]);
            }
        }
    }
}

// ---------------- K3: exclusive scan ----------------
#define SCAN_CH 1024
#define SCAN_NBLK ((N_NODES + SCAN_CH - 1) / SCAN_CH)   // 98

__global__ void scan1_kernel() {
    __shared__ int sh[SCAN_CH];
    int t = threadIdx.x;
    int g = blockIdx.x * SCAN_CH + t;
    int v = (g < N_NODES) ? g_counts[g] : 0;
    sh[t] = v;
    __syncthreads();
    for (int o = 1; o < SCAN_CH; o <<= 1) {
        int x = (t >= o) ? sh[t - o] : 0;
        __syncthreads();
        sh[t] += x;
        __syncthreads();
    }
    if (g < N_NODES) g_offs[g] = sh[t] - v;
    if (t == SCAN_CH - 1) g_bsum[blockIdx.x] = sh[t];
}

__global__ void scan2_kernel() {
    __shared__ int sh[128];
    int t = threadIdx.x;
    int v = (t < SCAN_NBLK) ? g_bsum[t] : 0;
    sh[t] = v;
    __syncthreads();
    for (int o = 1; o < 128; o <<= 1) {
        int x = (t >= o) ? sh[t - o] : 0;
        __syncthreads();
        sh[t] += x;
        __syncthreads();
    }
    if (t < SCAN_NBLK) g_bsum_ex[t] = sh[t] - v;
}

__global__ void scan3_kernel() {
    int g = blockIdx.x * SCAN_CH + threadIdx.x;
    if (g < N_NODES) {
        int v = g_offs[g] + g_bsum_ex[blockIdx.x];
        g_offs[g] = v;
        g_wpos[g] = v;
    }
}

// ---------------- K4: CSR scatter of src ids ----------------
__global__ void scatter_kernel(const int* __restrict__ ei) {
    int e = blockIdx.x * blockDim.x + threadIdx.x;
    if (e >= N_EDGES) return;
    int s = __ldg(&ei[e]);
    int d = __ldg(&ei[N_EDGES + e]);
    int pos = atomicAdd(&g_wpos[d], 1);
    g_csrc[pos] = s;
}

// ---------------- K5: fused logits+softmax+aggregate ----------------
// ONE 32-thread block per node: block slots free independently -> no
// intra-block warp imbalance; scheduler backfills continuously.
__global__ __launch_bounds__(32, 32)
void fused_node_kernel(const float* __restrict__ att,
                       const float* __restrict__ bias,
                       float* __restrict__ out) {
    int node = blockIdx.x;
    int lane = threadIdx.x;
    int beg = g_offs[node];
    int cnt = g_counts[node];

    float xr[8], at[8];
    cvt8(*reinterpret_cast<const uint4*>(g_xr_h + (size_t)node * 128 + lane * 4), xr);
    { const float4* atp = reinterpret_cast<const float4*>(att);
      float4 a0 = atp[lane * 2], a1 = atp[lane * 2 + 1];
      at[0] = a0.x; at[1] = a0.y; at[2] = a0.z; at[3] = a0.w;
      at[4] = a1.x; at[5] = a1.y; at[6] = a1.z; at[7] = a1.w; }

    float acc[8];
#pragma unroll
    for (int i = 0; i < 8; i++) acc[i] = 0.f;
    float denom = 0.f;

    int s_reg = (lane < cnt) ? g_csrc[beg + lane] : 0;
    int batch = 0;

    int j = 0;
    for (; j + 2 <= cnt; j += 2) {
        if ((j >> 5) != batch) {
            batch = j >> 5;
            int idx = beg + batch * 32 + lane;
            s_reg = (batch * 32 + lane < cnt) ? g_csrc[idx] : 0;
        }
        int s0 = __shfl_sync(0xffffffffu, s_reg, j & 31);
        int s1;
        if (((j + 1) >> 5) != batch) {
            batch = (j + 1) >> 5;
            int idx = beg + batch * 32 + lane;
            s_reg = (batch * 32 + lane < cnt) ? g_csrc[idx] : 0;
            s1 = __shfl_sync(0xffffffffu, s_reg, (j + 1) & 31);
        } else {
            s1 = __shfl_sync(0xffffffffu, s_reg, (j + 1) & 31);
        }

        uint4 u0 = *reinterpret_cast<const uint4*>(g_xl_h + (size_t)s0 * 128 + lane * 4);
        uint4 u1 = *reinterpret_cast<const uint4*>(g_xl_h + (size_t)s1 * 128 + lane * 4);

        float x0[8], x1[8];
        cvt8(u0, x0); cvt8(u1, x1);

        float p0 = 0.f, p1 = 0.f;
#pragma unroll
        for (int i = 0; i < 8; i++) {
            float h0 = x0[i] + xr[i]; h0 = h0 > 0.f ? h0 : NEG_SLOPE * h0;
            float h1 = x1[i] + xr[i]; h1 = h1 > 0.f ? h1 : NEG_SLOPE * h1;
            p0 = fmaf(at[i], h0, p0);
            p1 = fmaf(at[i], h1, p1);
        }
#pragma unroll
        for (int o = 16; o > 0; o >>= 1) {
            p0 += __shfl_xor_sync(0xffffffffu, p0, o);
            p1 += __shfl_xor_sync(0xffffffffu, p1, o);
        }
        float w0 = __expf(p0);
        float w1 = __expf(p1);
        denom += w0 + w1;
#pragma unroll
        for (int i = 0; i < 8; i++) {
            float t = fmaf(w0, x0[i], acc[i]);
            acc[i]  = fmaf(w1, x1[i], t);
        }
    }
    if (j < cnt) {
        if ((j >> 5) != batch) {
            batch = j >> 5;
            int idx = beg + batch * 32 + lane;
            s_reg = (batch * 32 + lane < cnt) ? g_csrc[idx] : 0;
        }
        int s0 = __shfl_sync(0xffffffffu, s_reg, j & 31);
        uint4 u0 = *reinterpret_cast<const uint4*>(g_xl_h + (size_t)s0 * 128 + lane * 4);
        float x0[8];
        cvt8(u0, x0);
        float p0 = 0.f;
#pragma unroll
        for (int i = 0; i < 8; i++) {
            float h0 = x0[i] + xr[i]; h0 = h0 > 0.f ? h0 : NEG_SLOPE * h0;
            p0 = fmaf(at[i], h0, p0);
        }
#pragma unroll
        for (int o = 16; o > 0; o >>= 1) p0 += __shfl_xor_sync(0xffffffffu, p0, o);
        float w0 = __expf(p0);
        denom += w0;
#pragma unroll
        for (int i = 0; i < 8; i++) acc[i] = fmaf(w0, x0[i], acc[i]);
    }

    float rd = 1.f / (denom + 1e-16f);
    const float4* bi = reinterpret_cast<const float4*>(bias);
    float4 bb0 = bi[lane * 2], bb1 = bi[lane * 2 + 1];
    float4 o0 = make_float4(fmaf(acc[0], rd, bb0.x), fmaf(acc[1], rd, bb0.y),
                            fmaf(acc[2], rd, bb0.z), fmaf(acc[3], rd, bb0.w));
    float4 o1 = make_float4(fmaf(acc[4], rd, bb1.x), fmaf(acc[5], rd, bb1.y),
                            fmaf(acc[6], rd, bb1.z), fmaf(acc[7], rd, bb1.w));
    float4* op = reinterpret_cast<float4*>(out + (size_t)node * D_OUT + lane * 8);
    op[0] = o0;
    op[1] = o1;
}

// ---------------- launch ----------------
extern "C" void kernel_launch(void* const* d_in, const int* in_sizes, int n_in,
                              void* d_out, int out_size) {
    const float* x    = (const float*)d_in[0];
    const int*   ei   = (const int*)d_in[1];
    const float* W_l  = (const float*)d_in[2];
    const float* b_l  = (const float*)d_in[3];
    const float* W_r  = (const float*)d_in[4];
    const float* b_r  = (const float*)d_in[5];
    const float* att  = (const float*)d_in[6];
    const float* bias = (const float*)d_in[7];
    float* out = (float*)d_out;

    init_kernel<<<(N_NODES + 255) / 256, 256>>>();
    hist_kernel<<<(N_EDGES + 255) / 256, 256>>>(ei);

    dim3 ggrid(2 * D_OUT / GBN, (N_NODES + GBM - 1) / GBM);   // (4, 782)
    gemm_tf32_kernel<<<ggrid, 256>>>(x, W_l, b_l, W_r, b_r);

    scan1_kernel<<<SCAN_NBLK, SCAN_CH>>>();
    scan2_kernel<<<1, 128>>>();
    scan3_kernel<<<SCAN_NBLK, SCAN_CH>>>();

    scatter_kernel<<<(N_EDGES + 255) / 256, 256>>>(ei);

    fused_node_kernel<<<N_NODES, 32>>>(att, bias, out);
}

// round 12
// speedup vs baseline: 1.7222x; 1.0342x over previous
#include <cuda_runtime.h>
#include <cuda_fp16.h>

#define N_NODES 100000
#define N_EDGES 1600000
#define D_IN    480
#define D_OUT   256
#define NEG_SLOPE 0.2f

// ---------------- scratch ----------------
__device__ unsigned g_xl_h[(size_t)N_NODES * (D_OUT / 2)];
__device__ unsigned g_xr_h[(size_t)N_NODES * (D_OUT / 2)];
__device__ int      g_counts[N_NODES];
__device__ int      g_offs[N_NODES];
__device__ int      g_wpos[N_NODES];
__device__ int      g_csrc[N_EDGES];
__device__ int      g_bsum[128];
__device__ int      g_bsum_ex[128];

__device__ __forceinline__ float tf32r(float x) {
    unsigned r;
    asm("cvt.rna.tf32.f32 %0, %1;" : "=r"(r) : "f"(x));
    return __uint_as_float(r);
}
__device__ __forceinline__ unsigned pack_half2(float lo, float hi) {
    unsigned r;
    asm("cvt.rn.f16x2.f32 %0, %1, %2;" : "=r"(r) : "f"(hi), "f"(lo));
    return r;
}
__device__ __forceinline__ float2 h2f2(unsigned u) {
    __half2 h = *reinterpret_cast<__half2*>(&u);
    return __half22float2(h);
}
__device__ __forceinline__ void cvt8(uint4 u, float* x) {
    float2 f;
    f = h2f2(u.x); x[0] = f.x; x[1] = f.y;
    f = h2f2(u.y); x[2] = f.x; x[3] = f.y;
    f = h2f2(u.z); x[4] = f.x; x[5] = f.y;
    f = h2f2(u.w); x[6] = f.x; x[7] = f.y;
}

// ---------------- K0: init ----------------
__global__ void init_kernel() {
    int i = blockIdx.x * blockDim.x + threadIdx.x;
    if (i < N_NODES) g_counts[i] = 0;
}

// ---------------- K2: dst histogram ----------------
__global__ void hist_kernel(const int* __restrict__ ei) {
    int e = blockIdx.x * blockDim.x + threadIdx.x;
    if (e < N_EDGES) atomicAdd(&g_counts[ei[N_EDGES + e]], 1);
}

// ---------------- K1: pipelined dual GEMM via tf32 mma.sync ----------------
#define GBM 128
#define GBN 128
#define GBK 16
#define PADA 20
#define PADB 136
#define NIT (D_IN / GBK)   // 30

__global__ __launch_bounds__(256, 2)
void gemm_tf32_kernel(const float* __restrict__ X,
                      const float* __restrict__ W_l, const float* __restrict__ b_l,
                      const float* __restrict__ W_r, const float* __restrict__ b_r) {
    __shared__ float As[2][GBM * PADA];
    __shared__ float Bs[2][GBK * PADB];

    int tx   = threadIdx.x;
    int lane = tx & 31;
    int wid  = tx >> 5;
    int warp_m = wid & 3;
    int warp_n = wid >> 2;

    int row0 = blockIdx.y * GBM;
    int col0 = blockIdx.x * GBN;

    const float* W; const float* bv; unsigned* Yh;
    int wc = col0;
    if (col0 < D_OUT) { W = W_l; bv = b_l; Yh = g_xl_h; }
    else              { W = W_r; bv = b_r; Yh = g_xr_h; wc = col0 - D_OUT; }

    int am  = (tx >> 2);
    int akq = (tx & 3);
    int bk  = (tx >> 5);
    int bnq = (tx & 31);

    float4 ra[2], rb[2];

    auto loadG = [&](int it) {
#pragma unroll
        for (int i = 0; i < 2; i++) {
            int m  = am + i * 64;
            int gr = row0 + m;
            float4 v = make_float4(0.f, 0.f, 0.f, 0.f);
            if (gr < N_NODES)
                v = *reinterpret_cast<const float4*>(X + (size_t)gr * D_IN + it * GBK + akq * 4);
            ra[i] = v;
        }
#pragma unroll
        for (int i = 0; i < 2; i++) {
            int k = bk + i * 8;
            rb[i] = *reinterpret_cast<const float4*>(W + (size_t)(it * GBK + k) * D_OUT + wc + bnq * 4);
        }
    };
    auto storeS = [&](int buf) {
#pragma unroll
        for (int i = 0; i < 2; i++) {
            int m = am + i * 64;
            float4 v = ra[i];
            v.x = tf32r(v.x); v.y = tf32r(v.y); v.z = tf32r(v.z); v.w = tf32r(v.w);
            *reinterpret_cast<float4*>(&As[buf][m * PADA + akq * 4]) = v;
        }
#pragma unroll
        for (int i = 0; i < 2; i++) {
            int k = bk + i * 8;
            float4 v = rb[i];
            v.x = tf32r(v.x); v.y = tf32r(v.y); v.z = tf32r(v.z); v.w = tf32r(v.w);
            *reinterpret_cast<float4*>(&Bs[buf][k * PADB + bnq * 4]) = v;
        }
    };

    float acc[2][8][4];
#pragma unroll
    for (int mt = 0; mt < 2; mt++)
#pragma unroll
        for (int nt = 0; nt < 8; nt++)
#pragma unroll
            for (int i = 0; i < 4; i++) acc[mt][nt][i] = 0.f;

    loadG(0);
    storeS(0);
    __syncthreads();

    for (int it = 0; it < NIT; it++) {
        int cur = it & 1;
        if (it + 1 < NIT) loadG(it + 1);

#pragma unroll
        for (int ks = 0; ks < 2; ks++) {
            int kk = ks * 8 + (lane & 3);
            unsigned a[2][4];
#pragma unroll
            for (int mt = 0; mt < 2; mt++) {
                int r = warp_m * 32 + mt * 16 + (lane >> 2);
                a[mt][0] = __float_as_uint(As[cur][r * PADA + kk]);
                a[mt][1] = __float_as_uint(As[cur][(r + 8) * PADA + kk]);
                a[mt][2] = __float_as_uint(As[cur][r * PADA + kk + 4]);
                a[mt][3] = __float_as_uint(As[cur][(r + 8) * PADA + kk + 4]);
            }
#pragma unroll
            for (int nt = 0; nt < 8; nt++) {
                int n = warp_n * 64 + nt * 8 + (lane >> 2);
                unsigned b0 = __float_as_uint(Bs[cur][kk * PADB + n]);
                unsigned b1 = __float_as_uint(Bs[cur][(kk + 4) * PADB + n]);
#pragma unroll
                for (int mt = 0; mt < 2; mt++) {
                    asm volatile(
                        "mma.sync.aligned.m16n8k8.row.col.f32.tf32.tf32.f32 "
                        "{%0,%1,%2,%3}, {%4,%5,%6,%7}, {%8,%9}, {%0,%1,%2,%3};"
                        : "+f"(acc[mt][nt][0]), "+f"(acc[mt][nt][1]),
                          "+f"(acc[mt][nt][2]), "+f"(acc[mt][nt][3])
                        : "r"(a[mt][0]), "r"(a[mt][1]), "r"(a[mt][2]), "r"(a[mt][3]),
                          "r"(b0), "r"(b1));
                }
            }
        }

        if (it + 1 < NIT) storeS((it + 1) & 1);
        __syncthreads();
    }

#pragma unroll
    for (int mt = 0; mt < 2; mt++) {
        int r = row0 + warp_m * 32 + mt * 16 + (lane >> 2);
#pragma unroll
        for (int nt = 0; nt < 8; nt++) {
            int c = wc + warp_n * 64 + nt * 8 + (lane & 3) * 2;
            if (r < N_NODES) {
                Yh[(size_t)r * (D_OUT / 2) + (c >> 1)] =
                    pack_half2(acc[mt][nt][0] + bv[c], acc[mt][nt][1] + bv[c + 1]);
            }
            if (r + 8 < N_NODES) {
                Yh[(size_t)(r + 8) * (D_OUT / 2) + (c >> 1)] =
                    pack_half2(acc[mt][nt][2] + bv[c], acc[mt][nt][3] + bv[c + 1]);
            }
        }
    }
}

// ---------------- K3: exclusive scan ----------------
#define SCAN_CH 1024
#define SCAN_NBLK ((N_NODES + SCAN_CH - 1) / SCAN_CH)   // 98

__global__ void scan1_kernel() {
    __shared__ int sh[SCAN_CH];
    int t = threadIdx.x;
    int g = blockIdx.x * SCAN_CH + t;
    int v = (g < N_NODES) ? g_counts[g] : 0;
    sh[t] = v;
    __syncthreads();
    for (int o = 1; o < SCAN_CH; o <<= 1) {
        int x = (t >= o) ? sh[t - o] : 0;
        __syncthreads();
        sh[t] += x;
        __syncthreads();
    }
    if (g < N_NODES) g_offs[g] = sh[t] - v;
    if (t == SCAN_CH - 1) g_bsum[blockIdx.x] = sh[t];
}

__global__ void scan2_kernel() {
    __shared__ int sh[128];
    int t = threadIdx.x;
    int v = (t < SCAN_NBLK) ? g_bsum[t] : 0;
    sh[t] = v;
    __syncthreads();
    for (int o = 1; o < 128; o <<= 1) {
        int x = (t >= o) ? sh[t - o] : 0;
        __syncthreads();
        sh[t] += x;
        __syncthreads();
    }
    if (t < SCAN_NBLK) g_bsum_ex[t] = sh[t] - v;
}

__global__ void scan3_kernel() {
    int g = blockIdx.x * SCAN_CH + threadIdx.x;
    if (g < N_NODES) {
        int v = g_offs[g] + g_bsum_ex[blockIdx.x];
        g_offs[g] = v;
        g_wpos[g] = v;
    }
}

// ---------------- K4: CSR scatter of src ids ----------------
__global__ void scatter_kernel(const int* __restrict__ ei) {
    int e = blockIdx.x * blockDim.x + threadIdx.x;
    if (e >= N_EDGES) return;
    int s = __ldg(&ei[e]);
    int d = __ldg(&ei[N_EDGES + e]);
    int pos = atomicAdd(&g_wpos[d], 1);
    g_csrc[pos] = s;
}

// ---------------- K5: fused logits+softmax+aggregate (one block = one warp = one node) ----------------
__global__ __launch_bounds__(32, 32)
void fused_node_kernel(const float* __restrict__ att,
                       const float* __restrict__ bias,
                       float* __restrict__ out) {
    int node = blockIdx.x;
    int lane = threadIdx.x;
    int beg = g_offs[node];
    int cnt = g_counts[node];

    float xr[8], at[8];
    cvt8(*reinterpret_cast<const uint4*>(g_xr_h + (size_t)node * 128 + lane * 4), xr);
    { const float4* atp = reinterpret_cast<const float4*>(att);
      float4 a0 = atp[lane * 2], a1 = atp[lane * 2 + 1];
      at[0] = a0.x; at[1] = a0.y; at[2] = a0.z; at[3] = a0.w;
      at[4] = a1.x; at[5] = a1.y; at[6] = a1.z; at[7] = a1.w; }

    float acc[8];
#pragma unroll
    for (int i = 0; i < 8; i++) acc[i] = 0.f;
    float denom = 0.f;

    int s_reg = (lane < cnt) ? g_csrc[beg + lane] : 0;
    int batch = 0;

    int j = 0;
    for (; j + 2 <= cnt; j += 2) {
        if ((j >> 5) != batch) {
            batch = j >> 5;
            int idx = beg + batch * 32 + lane;
            s_reg = (batch * 32 + lane < cnt) ? g_csrc[idx] : 0;
        }
        int s0 = __shfl_sync(0xffffffffu, s_reg, j & 31);
        int s1;
        if (((j + 1) >> 5) != batch) {
            batch = (j + 1) >> 5;
            int idx = beg + batch * 32 + lane;
            s_reg = (batch * 32 + lane < cnt) ? g_csrc[idx] : 0;
            s1 = __shfl_sync(0xffffffffu, s_reg, (j + 1) & 31);
        } else {
            s1 = __shfl_sync(0xffffffffu, s_reg, (j + 1) & 31);
        }

        uint4 u0 = *reinterpret_cast<const uint4*>(g_xl_h + (size_t)s0 * 128 + lane * 4);
        uint4 u1 = *reinterpret_cast<const uint4*>(g_xl_h + (size_t)s1 * 128 + lane * 4);

        float x0[8], x1[8];
        cvt8(u0, x0); cvt8(u1, x1);

        float p0 = 0.f, p1 = 0.f;
#pragma unroll
        for (int i = 0; i < 8; i++) {
            float h0 = x0[i] + xr[i]; h0 = h0 > 0.f ? h0 : NEG_SLOPE * h0;
            float h1 = x1[i] + xr[i]; h1 = h1 > 0.f ? h1 : NEG_SLOPE * h1;
            p0 = fmaf(at[i], h0, p0);
            p1 = fmaf(at[i], h1, p1);
        }
#pragma unroll
        for (int o = 16; o > 0; o >>= 1) {
            p0 += __shfl_xor_sync(0xffffffffu, p0, o);
            p1 += __shfl_xor_sync(0xffffffffu, p1, o);
        }
        float w0 = __expf(p0);
        float w1 = __expf(p1);
        denom += w0 + w1;
#pragma unroll
        for (int i = 0; i < 8; i++) {
            float t = fmaf(w0, x0[i], acc[i]);
            acc[i]  = fmaf(w1, x1[i], t);
        }
    }
    if (j < cnt) {
        if ((j >> 5) != batch) {
            batch = j >> 5;
            int idx = beg + batch * 32 + lane;
            s_reg = (batch * 32 + lane < cnt) ? g_csrc[idx] : 0;
        }
        int s0 = __shfl_sync(0xffffffffu, s_reg, j & 31);
        uint4 u0 = *reinterpret_cast<const uint4*>(g_xl_h + (size_t)s0 * 128 + lane * 4);
        float x0[8];
        cvt8(u0, x0);
        float p0 = 0.f;
#pragma unroll
        for (int i = 0; i < 8; i++) {
            float h0 = x0[i] + xr[i]; h0 = h0 > 0.f ? h0 : NEG_SLOPE * h0;
            p0 = fmaf(at[i], h0, p0);
        }
#pragma unroll
        for (int o = 16; o > 0; o >>= 1) p0 += __shfl_xor_sync(0xffffffffu, p0, o);
        float w0 = __expf(p0);
        denom += w0;
#pragma unroll
        for (int i = 0; i < 8; i++) acc[i] = fmaf(w0, x0[i], acc[i]);
    }

    float rd = 1.f / (denom + 1e-16f);
    const float4* bi = reinterpret_cast<const float4*>(bias);
    float4 bb0 = bi[lane * 2], bb1 = bi[lane * 2 + 1];
    float4 o0 = make_float4(fmaf(acc[0], rd, bb0.x), fmaf(acc[1], rd, bb0.y),
                            fmaf(acc[2], rd, bb0.z), fmaf(acc[3], rd, bb0.w));
    float4 o1 = make_float4(fmaf(acc[4], rd, bb1.x), fmaf(acc[5], rd, bb1.y),
                            fmaf(acc[6], rd, bb1.z), fmaf(acc[7], rd, bb1.w));
    float4* op = reinterpret_cast<float4*>(out + (size_t)node * D_OUT + lane * 8);
    op[0] = o0;
    op[1] = o1;
}

// ---------------- launch (forked capture: CSR chain || GEMM) ----------------
extern "C" void kernel_launch(void* const* d_in, const int* in_sizes, int n_in,
                              void* d_out, int out_size) {
    const float* x    = (const float*)d_in[0];
    const int*   ei   = (const int*)d_in[1];
    const float* W_l  = (const float*)d_in[2];
    const float* b_l  = (const float*)d_in[3];
    const float* W_r  = (const float*)d_in[4];
    const float* b_r  = (const float*)d_in[5];
    const float* att  = (const float*)d_in[6];
    const float* bias = (const float*)d_in[7];
    float* out = (float*)d_out;

    // lazy one-time host objects (not device memory; work per call is identical)
    static cudaStream_t s2 = nullptr;
    static cudaEvent_t evFork = nullptr, evJoin = nullptr;
    if (s2 == nullptr) {
        cudaStreamCreateWithFlags(&s2, cudaStreamNonBlocking);
        cudaEventCreateWithFlags(&evFork, cudaEventDisableTiming);
        cudaEventCreateWithFlags(&evJoin, cudaEventDisableTiming);
    }

    // fork: CSR build chain on s2, GEMM on the capture (default) stream
    cudaEventRecord(evFork, 0);
    cudaStreamWaitEvent(s2, evFork, 0);

    init_kernel<<<(N_NODES + 255) / 256, 256, 0, s2>>>();
    hist_kernel<<<(N_EDGES + 255) / 256, 256, 0, s2>>>(ei);
    scan1_kernel<<<SCAN_NBLK, SCAN_CH, 0, s2>>>();
    scan2_kernel<<<1, 128, 0, s2>>>();
    scan3_kernel<<<SCAN_NBLK, SCAN_CH, 0, s2>>>();
    scatter_kernel<<<(N_EDGES + 255) / 256, 256, 0, s2>>>(ei);

    dim3 ggrid(2 * D_OUT / GBN, (N_NODES + GBM - 1) / GBM);   // (4, 782)
    gemm_tf32_kernel<<<ggrid, 256>>>(x, W_l, b_l, W_r, b_r);

    // join: fused needs both branches
    cudaEventRecord(evJoin, s2);
    cudaStreamWaitEvent(0, evJoin, 0);

    fused_node_kernel<<<N_NODES, 32>>>(att, bias, out);
}

// round 13
// speedup vs baseline: 1.7247x; 1.0014x over previous
#include <cuda_runtime.h>
#include <cuda_fp16.h>

#define N_NODES 100000
#define N_EDGES 1600000
#define D_IN    480
#define D_OUT   256
#define NEG_SLOPE 0.2f

// ---------------- scratch ----------------
__device__ unsigned g_xl_h[(size_t)N_NODES * (D_OUT / 2)];
__device__ unsigned g_xr_h[(size_t)N_NODES * (D_OUT / 2)];
__device__ int      g_counts[N_NODES];
__device__ int      g_offs[N_NODES];
__device__ int      g_wpos[N_NODES];
__device__ int      g_csrc[N_EDGES];
__device__ int      g_bsum[128];

__device__ __forceinline__ float tf32r(float x) {
    unsigned r;
    asm("cvt.rna.tf32.f32 %0, %1;" : "=r"(r) : "f"(x));
    return __uint_as_float(r);
}
__device__ __forceinline__ unsigned pack_half2(float lo, float hi) {
    unsigned r;
    asm("cvt.rn.f16x2.f32 %0, %1, %2;" : "=r"(r) : "f"(hi), "f"(lo));
    return r;
}
__device__ __forceinline__ float2 h2f2(unsigned u) {
    __half2 h = *reinterpret_cast<__half2*>(&u);
    return __half22float2(h);
}
__device__ __forceinline__ void cvt8(uint4 u, float* x) {
    float2 f;
    f = h2f2(u.x); x[0] = f.x; x[1] = f.y;
    f = h2f2(u.y); x[2] = f.x; x[3] = f.y;
    f = h2f2(u.z); x[4] = f.x; x[5] = f.y;
    f = h2f2(u.w); x[6] = f.x; x[7] = f.y;
}

// ---------------- dst histogram ----------------
__global__ void hist_kernel(const int* __restrict__ ei) {
    int e = blockIdx.x * blockDim.x + threadIdx.x;
    if (e < N_EDGES) atomicAdd(&g_counts[ei[N_EDGES + e]], 1);
}

// ---------------- pipelined dual GEMM via tf32 mma.sync ----------------
#define GBM 128
#define GBN 128
#define GBK 16
#define PADA 20
#define PADB 136
#define NIT (D_IN / GBK)   // 30

__global__ __launch_bounds__(256, 2)
void gemm_tf32_kernel(const float* __restrict__ X,
                      const float* __restrict__ W_l, const float* __restrict__ b_l,
                      const float* __restrict__ W_r, const float* __restrict__ b_r) {
    __shared__ float As[2][GBM * PADA];
    __shared__ float Bs[2][GBK * PADB];

    int tx   = threadIdx.x;
    int lane = tx & 31;
    int wid  = tx >> 5;
    int warp_m = wid & 3;
    int warp_n = wid >> 2;

    int row0 = blockIdx.y * GBM;
    int col0 = blockIdx.x * GBN;

    const float* W; const float* bv; unsigned* Yh;
    int wc = col0;
    if (col0 < D_OUT) { W = W_l; bv = b_l; Yh = g_xl_h; }
    else              { W = W_r; bv = b_r; Yh = g_xr_h; wc = col0 - D_OUT; }

    int am  = (tx >> 2);
    int akq = (tx & 3);
    int bk  = (tx >> 5);
    int bnq = (tx & 31);

    float4 ra[2], rb[2];

    auto loadG = [&](int it) {
#pragma unroll
        for (int i = 0; i < 2; i++) {
            int m  = am + i * 64;
            int gr = row0 + m;
            float4 v = make_float4(0.f, 0.f, 0.f, 0.f);
            if (gr < N_NODES)
                v = *reinterpret_cast<const float4*>(X + (size_t)gr * D_IN + it * GBK + akq * 4);
            ra[i] = v;
        }
#pragma unroll
        for (int i = 0; i < 2; i++) {
            int k = bk + i * 8;
            rb[i] = *reinterpret_cast<const float4*>(W + (size_t)(it * GBK + k) * D_OUT + wc + bnq * 4);
        }
    };
    auto storeS = [&](int buf) {
#pragma unroll
        for (int i = 0; i < 2; i++) {
            int m = am + i * 64;
            float4 v = ra[i];
            v.x = tf32r(v.x); v.y = tf32r(v.y); v.z = tf32r(v.z); v.w = tf32r(v.w);
            *reinterpret_cast<float4*>(&As[buf][m * PADA + akq * 4]) = v;
        }
#pragma unroll
        for (int i = 0; i < 2; i++) {
            int k = bk + i * 8;
            float4 v = rb[i];
            v.x = tf32r(v.x); v.y = tf32r(v.y); v.z = tf32r(v.z); v.w = tf32r(v.w);
            *reinterpret_cast<float4*>(&Bs[buf][k * PADB + bnq * 4]) = v;
        }
    };

    float acc[2][8][4];
#pragma unroll
    for (int mt = 0; mt < 2; mt++)
#pragma unroll
        for (int nt = 0; nt < 8; nt++)
#pragma unroll
            for (int i = 0; i < 4; i++) acc[mt][nt][i] = 0.f;

    loadG(0);
    storeS(0);
    __syncthreads();

    for (int it = 0; it < NIT; it++) {
        int cur = it & 1;
        if (it + 1 < NIT) loadG(it + 1);

#pragma unroll
        for (int ks = 0; ks < 2; ks++) {
            int kk = ks * 8 + (lane & 3);
            unsigned a[2][4];
#pragma unroll
            for (int mt = 0; mt < 2; mt++) {
                int r = warp_m * 32 + mt * 16 + (lane >> 2);
                a[mt][0] = __float_as_uint(As[cur][r * PADA + kk]);
                a[mt][1] = __float_as_uint(As[cur][(r + 8) * PADA + kk]);
                a[mt][2] = __float_as_uint(As[cur][r * PADA + kk + 4]);
                a[mt][3] = __float_as_uint(As[cur][(r + 8) * PADA + kk + 4]);
            }
#pragma unroll
            for (int nt = 0; nt < 8; nt++) {
                int n = warp_n * 64 + nt * 8 + (lane >> 2);
                unsigned b0 = __float_as_uint(Bs[cur][kk * PADB + n]);
                unsigned b1 = __float_as_uint(Bs[cur][(kk + 4) * PADB + n]);
#pragma unroll
                for (int mt = 0; mt < 2; mt++) {
                    asm volatile(
                        "mma.sync.aligned.m16n8k8.row.col.f32.tf32.tf32.f32 "
                        "{%0,%1,%2,%3}, {%4,%5,%6,%7}, {%8,%9}, {%0,%1,%2,%3};"
                        : "+f"(acc[mt][nt][0]), "+f"(acc[mt][nt][1]),
                          "+f"(acc[mt][nt][2]), "+f"(acc[mt][nt][3])
                        : "r"(a[mt][0]), "r"(a[mt][1]), "r"(a[mt][2]), "r"(a[mt][3]),
                          "r"(b0), "r"(b1));
                }
            }
        }

        if (it + 1 < NIT) storeS((it + 1) & 1);
        __syncthreads();
    }

#pragma unroll
    for (int mt = 0; mt < 2; mt++) {
        int r = row0 + warp_m * 32 + mt * 16 + (lane >> 2);
#pragma unroll
        for (int nt = 0; nt < 8; nt++) {
            int c = wc + warp_n * 64 + nt * 8 + (lane & 3) * 2;
            if (r < N_NODES) {
                Yh[(size_t)r * (D_OUT / 2) + (c >> 1)] =
                    pack_half2(acc[mt][nt][0] + bv[c], acc[mt][nt][1] + bv[c + 1]);
            }
            if (r + 8 < N_NODES) {
                Yh[(size_t)(r + 8) * (D_OUT / 2) + (c >> 1)] =
                    pack_half2(acc[mt][nt][2] + bv[c], acc[mt][nt][3] + bv[c + 1]);
            }
        }
    }
}

// ---------------- exclusive scan (2 kernels) ----------------
#define SCAN_CH 1024
#define SCAN_NBLK ((N_NODES + SCAN_CH - 1) / SCAN_CH)   // 98

__global__ void scan1_kernel() {
    __shared__ int sh[SCAN_CH];
    int t = threadIdx.x;
    int g = blockIdx.x * SCAN_CH + t;
    int v = (g < N_NODES) ? g_counts[g] : 0;
    sh[t] = v;
    __syncthreads();
    for (int o = 1; o < SCAN_CH; o <<= 1) {
        int x = (t >= o) ? sh[t - o] : 0;
        __syncthreads();
        sh[t] += x;
        __syncthreads();
    }
    if (g < N_NODES) g_offs[g] = sh[t] - v;
    if (t == SCAN_CH - 1) g_bsum[blockIdx.x] = sh[t];
}

// scan3: each block computes its own block-prefix (parallel 128-wide reduce of g_bsum)
__global__ void scan3_kernel() {
    __shared__ int sb[128];
    int t = threadIdx.x;
    if (t < 128) sb[t] = (t < blockIdx.x && t < SCAN_NBLK) ? g_bsum[t] : 0;
    __syncthreads();
    if (t < 64) sb[t] += sb[t + 64];
    __syncthreads();
    if (t < 32) {
        int v = sb[t] + sb[t + 32];
#pragma unroll
        for (int o = 16; o > 0; o >>= 1) v += __shfl_xor_sync(0xffffffffu, v, o);
        if (t == 0) sb[0] = v;
    }
    __syncthreads();
    int base = sb[0];
    int g = blockIdx.x * SCAN_CH + t;
    if (g < N_NODES) {
        int v = g_offs[g] + base;
        g_offs[g] = v;
        g_wpos[g] = v;
    }
}

// ---------------- CSR scatter of src ids ----------------
__global__ void scatter_kernel(const int* __restrict__ ei) {
    int e = blockIdx.x * blockDim.x + threadIdx.x;
    if (e >= N_EDGES) return;
    int s = __ldg(&ei[e]);
    int d = __ldg(&ei[N_EDGES + e]);
    int pos = atomicAdd(&g_wpos[d], 1);
    g_csrc[pos] = s;
}

// ---------------- fused logits+softmax+aggregate (one block = one warp = one node) ----------------
__global__ __launch_bounds__(32, 32)
void fused_node_kernel(const float* __restrict__ att,
                       const float* __restrict__ bias,
                       float* __restrict__ out) {
    int node = blockIdx.x;
    int lane = threadIdx.x;
    int beg = g_offs[node];
    int cnt = g_counts[node];

    float xr[8], at[8];
    cvt8(*reinterpret_cast<const uint4*>(g_xr_h + (size_t)node * 128 + lane * 4), xr);
    { const float4* atp = reinterpret_cast<const float4*>(att);
      float4 a0 = atp[lane * 2], a1 = atp[lane * 2 + 1];
      at[0] = a0.x; at[1] = a0.y; at[2] = a0.z; at[3] = a0.w;
      at[4] = a1.x; at[5] = a1.y; at[6] = a1.z; at[7] = a1.w; }

    float acc[8];
#pragma unroll
    for (int i = 0; i < 8; i++) acc[i] = 0.f;
    float denom = 0.f;

    int s_reg = (lane < cnt) ? g_csrc[beg + lane] : 0;
    int batch = 0;

    int j = 0;
    for (; j + 2 <= cnt; j += 2) {
        if ((j >> 5) != batch) {
            batch = j >> 5;
            int idx = beg + batch * 32 + lane;
            s_reg = (batch * 32 + lane < cnt) ? g_csrc[idx] : 0;
        }
        int s0 = __shfl_sync(0xffffffffu, s_reg, j & 31);
        int s1;
        if (((j + 1) >> 5) != batch) {
            batch = (j + 1) >> 5;
            int idx = beg + batch * 32 + lane;
            s_reg = (batch * 32 + lane < cnt) ? g_csrc[idx] : 0;
            s1 = __shfl_sync(0xffffffffu, s_reg, (j + 1) & 31);
        } else {
            s1 = __shfl_sync(0xffffffffu, s_reg, (j + 1) & 31);
        }

        uint4 u0 = *reinterpret_cast<const uint4*>(g_xl_h + (size_t)s0 * 128 + lane * 4);
        uint4 u1 = *reinterpret_cast<const uint4*>(g_xl_h + (size_t)s1 * 128 + lane * 4);

        float x0[8], x1[8];
        cvt8(u0, x0); cvt8(u1, x1);

        float p0 = 0.f, p1 = 0.f;
#pragma unroll
        for (int i = 0; i < 8; i++) {
            float h0 = x0[i] + xr[i]; h0 = h0 > 0.f ? h0 : NEG_SLOPE * h0;
            float h1 = x1[i] + xr[i]; h1 = h1 > 0.f ? h1 : NEG_SLOPE * h1;
            p0 = fmaf(at[i], h0, p0);
            p1 = fmaf(at[i], h1, p1);
        }
#pragma unroll
        for (int o = 16; o > 0; o >>= 1) {
            p0 += __shfl_xor_sync(0xffffffffu, p0, o);
            p1 += __shfl_xor_sync(0xffffffffu, p1, o);
        }
        float w0 = __expf(p0);
        float w1 = __expf(p1);
        denom += w0 + w1;
#pragma unroll
        for (int i = 0; i < 8; i++) {
            float t = fmaf(w0, x0[i], acc[i]);
            acc[i]  = fmaf(w1, x1[i], t);
        }
    }
    if (j < cnt) {
        if ((j >> 5) != batch) {
            batch = j >> 5;
            int idx = beg + batch * 32 + lane;
            s_reg = (batch * 32 + lane < cnt) ? g_csrc[idx] : 0;
        }
        int s0 = __shfl_sync(0xffffffffu, s_reg, j & 31);
        uint4 u0 = *reinterpret_cast<const uint4*>(g_xl_h + (size_t)s0 * 128 + lane * 4);
        float x0[8];
        cvt8(u0, x0);
        float p0 = 0.f;
#pragma unroll
        for (int i = 0; i < 8; i++) {
            float h0 = x0[i] + xr[i]; h0 = h0 > 0.f ? h0 : NEG_SLOPE * h0;
            p0 = fmaf(at[i], h0, p0);
        }
#pragma unroll
        for (int o = 16; o > 0; o >>= 1) p0 += __shfl_xor_sync(0xffffffffu, p0, o);
        float w0 = __expf(p0);
        denom += w0;
#pragma unroll
        for (int i = 0; i < 8; i++) acc[i] = fmaf(w0, x0[i], acc[i]);
    }

    float rd = 1.f / (denom + 1e-16f);
    const float4* bi = reinterpret_cast<const float4*>(bias);
    float4 bb0 = bi[lane * 2], bb1 = bi[lane * 2 + 1];
    float4 o0 = make_float4(fmaf(acc[0], rd, bb0.x), fmaf(acc[1], rd, bb0.y),
                            fmaf(acc[2], rd, bb0.z), fmaf(acc[3], rd, bb0.w));
    float4 o1 = make_float4(fmaf(acc[4], rd, bb1.x), fmaf(acc[5], rd, bb1.y),
                            fmaf(acc[6], rd, bb1.z), fmaf(acc[7], rd, bb1.w));
    float4* op = reinterpret_cast<float4*>(out + (size_t)node * D_OUT + lane * 8);
    op[0] = o0;
    op[1] = o1;
}

// ---------------- launch (forked capture: CSR chain || GEMM) ----------------
extern "C" void kernel_launch(void* const* d_in, const int* in_sizes, int n_in,
                              void* d_out, int out_size) {
    const float* x    = (const float*)d_in[0];
    const int*   ei   = (const int*)d_in[1];
    const float* W_l  = (const float*)d_in[2];
    const float* b_l  = (const float*)d_in[3];
    const float* W_r  = (const float*)d_in[4];
    const float* b_r  = (const float*)d_in[5];
    const float* att  = (const float*)d_in[6];
    const float* bias = (const float*)d_in[7];
    float* out = (float*)d_out;

    // lazy one-time host objects (not device memory; per-call work identical)
    static cudaStream_t s2 = nullptr;
    static cudaEvent_t evFork = nullptr, evJoin = nullptr;
    static int* counts_ptr = nullptr;
    if (s2 == nullptr) {
        cudaStreamCreateWithFlags(&s2, cudaStreamNonBlocking);
        cudaEventCreateWithFlags(&evFork, cudaEventDisableTiming);
        cudaEventCreateWithFlags(&evJoin, cudaEventDisableTiming);
        cudaGetSymbolAddress((void**)&counts_ptr, g_counts);
    }

    // fork: CSR build chain on s2, GEMM on the capture (default) stream
    cudaEventRecord(evFork, 0);
    cudaStreamWaitEvent(s2, evFork, 0);

    cudaMemsetAsync(counts_ptr, 0, N_NODES * sizeof(int), s2);
    hist_kernel<<<(N_EDGES + 255) / 256, 256, 0, s2>>>(ei);     // kernel launch 1
    scan1_kernel<<<SCAN_NBLK, SCAN_CH, 0, s2>>>();              // 2
    scan3_kernel<<<SCAN_NBLK, SCAN_CH, 0, s2>>>();              // 3

    dim3 ggrid(2 * D_OUT / GBN, (N_NODES + GBM - 1) / GBM);     // (4, 782)
    gemm_tf32_kernel<<<ggrid, 256>>>(x, W_l, b_l, W_r, b_r);    // 4  <- ncu slot

    scatter_kernel<<<(N_EDGES + 255) / 256, 256, 0, s2>>>(ei);  // 5

    // join: fused needs both branches
    cudaEventRecord(evJoin, s2);
    cudaStreamWaitEvent(0, evJoin, 0);

    fused_node_kernel<<<N_NODES, 32>>>(att, bias, out);         // 6
}

// round 14
// speedup vs baseline: 1.8170x; 1.0535x over previous
#include <cuda_runtime.h>
#include <cuda_fp16.h>

#define N_NODES 100000
#define N_EDGES 1600000
#define D_IN    480
#define D_OUT   256
#define NEG_SLOPE 0.2f

// ---------------- scratch ----------------
__device__ unsigned g_xl_h[(size_t)N_NODES * (D_OUT / 2)];
__device__ unsigned g_xr_h[(size_t)N_NODES * (D_OUT / 2)];
__device__ int      g_counts[N_NODES];
__device__ int      g_offs[N_NODES];
__device__ int      g_wpos[N_NODES];
__device__ int      g_csrc[N_EDGES];
__device__ int      g_bsum[128];

__device__ __forceinline__ unsigned pack_half2(float lo, float hi) {
    unsigned r;
    asm("cvt.rn.f16x2.f32 %0, %1, %2;" : "=r"(r) : "f"(hi), "f"(lo));
    return r;
}
__device__ __forceinline__ float2 h2f2(unsigned u) {
    __half2 h = *reinterpret_cast<__half2*>(&u);
    return __half22float2(h);
}
__device__ __forceinline__ void cvt8(uint4 u, float* x) {
    float2 f;
    f = h2f2(u.x); x[0] = f.x; x[1] = f.y;
    f = h2f2(u.y); x[2] = f.x; x[3] = f.y;
    f = h2f2(u.z); x[4] = f.x; x[5] = f.y;
    f = h2f2(u.w); x[6] = f.x; x[7] = f.y;
}
__device__ __forceinline__ void ldsm_x4(unsigned& r0, unsigned& r1,
                                        unsigned& r2, unsigned& r3, unsigned addr) {
    asm volatile("ldmatrix.sync.aligned.m8n8.x4.shared.b16 {%0,%1,%2,%3}, [%4];"
                 : "=r"(r0), "=r"(r1), "=r"(r2), "=r"(r3) : "r"(addr));
}

// ---------------- dst histogram ----------------
__global__ void hist_kernel(const int* __restrict__ ei) {
    int e = blockIdx.x * blockDim.x + threadIdx.x;
    if (e < N_EDGES) atomicAdd(&g_counts[ei[N_EDGES + e]], 1);
}

// ---------------- pipelined dual GEMM: fp16 mma.m16n8k16 + ldmatrix ----------------
// Block 128x128, BK=32, 2-stage. 8 warps, each 32(m) x 64(n).
// A smem: [m][k] halves, row stride 80B (5x16B -> conflict-free LDSM phases).
// B smem: transposed [n][k] halves, same stride.
#define GBM 128
#define GBN 128
#define GBK 32
#define SRB 80                  // row stride in bytes
#define STG_BYTES (128 * SRB)   // 10240 per stage
#define NIT (D_IN / GBK)        // 15

__global__ __launch_bounds__(256, 2)
void gemm_fp16_kernel(const float* __restrict__ X,
                      const float* __restrict__ W_l, const float* __restrict__ b_l,
                      const float* __restrict__ W_r, const float* __restrict__ b_r) {
    __shared__ __align__(16) char Asm[2][STG_BYTES];
    __shared__ __align__(16) char Bsm[2][STG_BYTES];

    int tx   = threadIdx.x;
    int lane = tx & 31;
    int wid  = tx >> 5;
    int warp_m = wid & 3;       // 0..3
    int warp_n = wid >> 2;      // 0..1
    int gid = lane >> 2;        // 0..7
    int tg  = lane & 3;         // 0..3

    int row0 = blockIdx.y * GBM;
    int col0 = blockIdx.x * GBN;

    const float* W; const float* bv; unsigned* Yh;
    int wc = col0;
    if (col0 < D_OUT) { W = W_l; bv = b_l; Yh = g_xl_h; }
    else              { W = W_r; bv = b_r; Yh = g_xr_h; wc = col0 - D_OUT; }

    unsigned a_base = (unsigned)__cvta_generic_to_shared(&Asm[0][0]);
    unsigned b_base = (unsigned)__cvta_generic_to_shared(&Bsm[0][0]);

    // A loader: 4 float4/thread. f = tx + i*256 -> m = f>>3, kq = f&7 (4-float quads)
    int am  = tx >> 3;          // 0..31, +32 per i
    int akq = tx & 7;
    // B loader: kp = tx&15 (k-pair), nq = tx>>4 (0..15), +16 per i
    int bkp = tx & 15;
    int bnq = tx >> 4;

    float4 ra[4];
    float4 rb[2][2];

    auto loadG = [&](int it) {
        int k0 = it * GBK;
#pragma unroll
        for (int i = 0; i < 4; i++) {
            int m  = am + i * 32;
            int gr = row0 + m;
            float4 v = make_float4(0.f, 0.f, 0.f, 0.f);
            if (gr < N_NODES)
                v = *reinterpret_cast<const float4*>(X + (size_t)gr * D_IN + k0 + akq * 4);
            ra[i] = v;
        }
#pragma unroll
        for (int i = 0; i < 2; i++) {
            int nq = bnq + i * 16;
            rb[i][0] = *reinterpret_cast<const float4*>(W + (size_t)(k0 + 2 * bkp) * D_OUT + wc + nq * 4);
            rb[i][1] = *reinterpret_cast<const float4*>(W + (size_t)(k0 + 2 * bkp + 1) * D_OUT + wc + nq * 4);
        }
    };
    auto storeS = [&](int buf) {
        char* Ab = Asm[buf];
        char* Bb = Bsm[buf];
#pragma unroll
        for (int i = 0; i < 4; i++) {
            int m = am + i * 32;
            float4 v = ra[i];
            uint2 p = make_uint2(pack_half2(v.x, v.y), pack_half2(v.z, v.w));
            *reinterpret_cast<uint2*>(Ab + m * SRB + akq * 8) = p;
        }
#pragma unroll
        for (int i = 0; i < 2; i++) {
            int nq = bnq + i * 16;
            const float* lo = &rb[i][0].x;
            const float* hi = &rb[i][1].x;
#pragma unroll
            for (int j = 0; j < 4; j++) {
                *reinterpret_cast<unsigned*>(Bb + (nq * 4 + j) * SRB + bkp * 4) =
                    pack_half2(lo[j], hi[j]);
            }
        }
    };

    float acc[2][8][4];
#pragma unroll
    for (int mt = 0; mt < 2; mt++)
#pragma unroll
        for (int nt = 0; nt < 8; nt++)
#pragma unroll
            for (int i = 0; i < 4; i++) acc[mt][nt][i] = 0.f;

    loadG(0);
    storeS(0);
    __syncthreads();

    // LDSM address pattern: row = base + (lane&15), chunk = kc0 + (lane>>4)
    int lrow = lane & 15;
    int lchk = lane >> 4;

    for (int it = 0; it < NIT; it++) {
        int cur = it & 1;
        unsigned aA = a_base + cur * STG_BYTES;
        unsigned aB = b_base + cur * STG_BYTES;
        if (it + 1 < NIT) loadG(it + 1);

#pragma unroll
        for (int ks = 0; ks < 2; ks++) {
            int kc0 = ks * 2;
            unsigned a[2][4];
#pragma unroll
            for (int mt = 0; mt < 2; mt++) {
                int m_base = warp_m * 32 + mt * 16;
                unsigned addr = aA + (m_base + lrow) * SRB + (kc0 + lchk) * 16;
                ldsm_x4(a[mt][0], a[mt][1], a[mt][2], a[mt][3], addr);
            }
            unsigned br[4][4];
#pragma unroll
            for (int pr = 0; pr < 4; pr++) {
                int n_base = warp_n * 64 + pr * 16;
                unsigned addr = aB + (n_base + lrow) * SRB + (kc0 + lchk) * 16;
                ldsm_x4(br[pr][0], br[pr][1], br[pr][2], br[pr][3], addr);
            }
#pragma unroll
            for (int pr = 0; pr < 4; pr++) {
#pragma unroll
                for (int sub = 0; sub < 2; sub++) {
                    int nt = pr * 2 + sub;
                    unsigned b0 = br[pr][sub];       // (n sub-half, k0-7)
                    unsigned b1 = br[pr][sub + 2];   // (n sub-half, k8-15)
#pragma unroll
                    for (int mt = 0; mt < 2; mt++) {
                        asm volatile(
                            "mma.sync.aligned.m16n8k16.row.col.f32.f16.f16.f32 "
                            "{%0,%1,%2,%3}, {%4,%5,%6,%7}, {%8,%9}, {%0,%1,%2,%3};"
                            : "+f"(acc[mt][nt][0]), "+f"(acc[mt][nt][1]),
                              "+f"(acc[mt][nt][2]), "+f"(acc[mt][nt][3])
                            : "r"(a[mt][0]), "r"(a[mt][1]), "r"(a[mt][2]), "r"(a[mt][3]),
                              "r"(b0), "r"(b1));
                    }
                }
            }
        }

        if (it + 1 < NIT) storeS((it + 1) & 1);
        __syncthreads();
    }

#pragma unroll
    for (int mt = 0; mt < 2; mt++) {
        int r = row0 + warp_m * 32 + mt * 16 + gid;
#pragma unroll
        for (int nt = 0; nt < 8; nt++) {
            int c = wc + warp_n * 64 + nt * 8 + tg * 2;
            if (r < N_NODES) {
                Yh[(size_t)r * (D_OUT / 2) + (c >> 1)] =
                    pack_half2(acc[mt][nt][0] + bv[c], acc[mt][nt][1] + bv[c + 1]);
            }
            if (r + 8 < N_NODES) {
                Yh[(size_t)(r + 8) * (D_OUT / 2) + (c >> 1)] =
                    pack_half2(acc[mt][nt][2] + bv[c], acc[mt][nt][3] + bv[c + 1]);
            }
        }
    }
}

// ---------------- exclusive scan (2 kernels) ----------------
#define SCAN_CH 1024
#define SCAN_NBLK ((N_NODES + SCAN_CH - 1) / SCAN_CH)   // 98

__global__ void scan1_kernel() {
    __shared__ int sh[SCAN_CH];
    int t = threadIdx.x;
    int g = blockIdx.x * SCAN_CH + t;
    int v = (g < N_NODES) ? g_counts[g] : 0;
    sh[t] = v;
    __syncthreads();
    for (int o = 1; o < SCAN_CH; o <<= 1) {
        int x = (t >= o) ? sh[t - o] : 0;
        __syncthreads();
        sh[t] += x;
        __syncthreads();
    }
    if (g < N_NODES) g_offs[g] = sh[t] - v;
    if (t == SCAN_CH - 1) g_bsum[blockIdx.x] = sh[t];
}

__global__ void scan3_kernel() {
    __shared__ int sb[128];
    int t = threadIdx.x;
    if (t < 128) sb[t] = (t < blockIdx.x && t < SCAN_NBLK) ? g_bsum[t] : 0;
    __syncthreads();
    if (t < 64) sb[t] += sb[t + 64];
    __syncthreads();
    if (t < 32) {
        int v = sb[t] + sb[t + 32];
#pragma unroll
        for (int o = 16; o > 0; o >>= 1) v += __shfl_xor_sync(0xffffffffu, v, o);
        if (t == 0) sb[0] = v;
    }
    __syncthreads();
    int base = sb[0];
    int g = blockIdx.x * SCAN_CH + t;
    if (g < N_NODES) {
        int v = g_offs[g] + base;
        g_offs[g] = v;
        g_wpos[g] = v;
    }
}

// ---------------- CSR scatter of src ids ----------------
__global__ void scatter_kernel(const int* __restrict__ ei) {
    int e = blockIdx.x * blockDim.x + threadIdx.x;
    if (e >= N_EDGES) return;
    int s = __ldg(&ei[e]);
    int d = __ldg(&ei[N_EDGES + e]);
    int pos = atomicAdd(&g_wpos[d], 1);
    g_csrc[pos] = s;
}

// ---------------- fused logits+softmax+aggregate (one block = one warp = one node) ----------------
__global__ __launch_bounds__(32, 32)
void fused_node_kernel(const float* __restrict__ att,
                       const float* __restrict__ bias,
                       float* __restrict__ out) {
    int node = blockIdx.x;
    int lane = threadIdx.x;
    int beg = g_offs[node];
    int cnt = g_counts[node];

    float xr[8], at[8];
    cvt8(*reinterpret_cast<const uint4*>(g_xr_h + (size_t)node * 128 + lane * 4), xr);
    { const float4* atp = reinterpret_cast<const float4*>(att);
      float4 a0 = atp[lane * 2], a1 = atp[lane * 2 + 1];
      at[0] = a0.x; at[1] = a0.y; at[2] = a0.z; at[3] = a0.w;
      at[4] = a1.x; at[5] = a1.y; at[6] = a1.z; at[7] = a1.w; }

    float acc[8];
#pragma unroll
    for (int i = 0; i < 8; i++) acc[i] = 0.f;
    float denom = 0.f;

    int s_reg = (lane < cnt) ? g_csrc[beg + lane] : 0;
    int batch = 0;

    int j = 0;
    for (; j + 2 <= cnt; j += 2) {
        if ((j >> 5) != batch) {
            batch = j >> 5;
            int idx = beg + batch * 32 + lane;
            s_reg = (batch * 32 + lane < cnt) ? g_csrc[idx] : 0;
        }
        int s0 = __shfl_sync(0xffffffffu, s_reg, j & 31);
        int s1;
        if (((j + 1) >> 5) != batch) {
            batch = (j + 1) >> 5;
            int idx = beg + batch * 32 + lane;
            s_reg = (batch * 32 + lane < cnt) ? g_csrc[idx] : 0;
            s1 = __shfl_sync(0xffffffffu, s_reg, (j + 1) & 31);
        } else {
            s1 = __shfl_sync(0xffffffffu, s_reg, (j + 1) & 31);
        }

        uint4 u0 = *reinterpret_cast<const uint4*>(g_xl_h + (size_t)s0 * 128 + lane * 4);
        uint4 u1 = *reinterpret_cast<const uint4*>(g_xl_h + (size_t)s1 * 128 + lane * 4);

        float x0[8], x1[8];
        cvt8(u0, x0); cvt8(u1, x1);

        float p0 = 0.f, p1 = 0.f;
#pragma unroll
        for (int i = 0; i < 8; i++) {
            float h0 = x0[i] + xr[i]; h0 = h0 > 0.f ? h0 : NEG_SLOPE * h0;
            float h1 = x1[i] + xr[i]; h1 = h1 > 0.f ? h1 : NEG_SLOPE * h1;
            p0 = fmaf(at[i], h0, p0);
            p1 = fmaf(at[i], h1, p1);
        }
#pragma unroll
        for (int o = 16; o > 0; o >>= 1) {
            p0 += __shfl_xor_sync(0xffffffffu, p0, o);
            p1 += __shfl_xor_sync(0xffffffffu, p1, o);
        }
        float w0 = __expf(p0);
        float w1 = __expf(p1);
        denom += w0 + w1;
#pragma unroll
        for (int i = 0; i < 8; i++) {
            float t = fmaf(w0, x0[i], acc[i]);
            acc[i]  = fmaf(w1, x1[i], t);
        }
    }
    if (j < cnt) {
        if ((j >> 5) != batch) {
            batch = j >> 5;
            int idx = beg + batch * 32 + lane;
            s_reg = (batch * 32 + lane < cnt) ? g_csrc[idx] : 0;
        }
        int s0 = __shfl_sync(0xffffffffu, s_reg, j & 31);
        uint4 u0 = *reinterpret_cast<const uint4*>(g_xl_h + (size_t)s0 * 128 + lane * 4);
        float x0[8];
        cvt8(u0, x0);
        float p0 = 0.f;
#pragma unroll
        for (int i = 0; i < 8; i++) {
            float h0 = x0[i] + xr[i]; h0 = h0 > 0.f ? h0 : NEG_SLOPE * h0;
            p0 = fmaf(at[i], h0, p0);
        }
#pragma unroll
        for (int o = 16; o > 0; o >>= 1) p0 += __shfl_xor_sync(0xffffffffu, p0, o);
        float w0 = __expf(p0);
        denom += w0;
#pragma unroll
        for (int i = 0; i < 8; i++) acc[i] = fmaf(w0, x0[i], acc[i]);
    }

    float rd = 1.f / (denom + 1e-16f);
    const float4* bi = reinterpret_cast<const float4*>(bias);
    float4 bb0 = bi[lane * 2], bb1 = bi[lane * 2 + 1];
    float4 o0 = make_float4(fmaf(acc[0], rd, bb0.x), fmaf(acc[1], rd, bb0.y),
                            fmaf(acc[2], rd, bb0.z), fmaf(acc[3], rd, bb0.w));
    float4 o1 = make_float4(fmaf(acc[4], rd, bb1.x), fmaf(acc[5], rd, bb1.y),
                            fmaf(acc[6], rd, bb1.z), fmaf(acc[7], rd, bb1.w));
    float4* op = reinterpret_cast<float4*>(out + (size_t)node * D_OUT + lane * 8);
    op[0] = o0;
    op[1] = o1;
}

// ---------------- launch (forked capture: CSR chain || GEMM) ----------------
extern "C" void kernel_launch(void* const* d_in, const int* in_sizes, int n_in,
                              void* d_out, int out_size) {
    const float* x    = (const float*)d_in[0];
    const int*   ei   = (const int*)d_in[1];
    const float* W_l  = (const float*)d_in[2];
    const float* b_l  = (const float*)d_in[3];
    const float* W_r  = (const float*)d_in[4];
    const float* b_r  = (const float*)d_in[5];
    const float* att  = (const float*)d_in[6];
    const float* bias = (const float*)d_in[7];
    float* out = (float*)d_out;

    static cudaStream_t s2 = nullptr;
    static cudaEvent_t evFork = nullptr, evJoin = nullptr;
    static int* counts_ptr = nullptr;
    if (s2 == nullptr) {
        cudaStreamCreateWithFlags(&s2, cudaStreamNonBlocking);
        cudaEventCreateWithFlags(&evFork, cudaEventDisableTiming);
        cudaEventCreateWithFlags(&evJoin, cudaEventDisableTiming);
        cudaGetSymbolAddress((void**)&counts_ptr, g_counts);
    }

    cudaEventRecord(evFork, 0);
    cudaStreamWaitEvent(s2, evFork, 0);

    cudaMemsetAsync(counts_ptr, 0, N_NODES * sizeof(int), s2);
    hist_kernel<<<(N_EDGES + 255) / 256, 256, 0, s2>>>(ei);     // 1
    scan1_kernel<<<SCAN_NBLK, SCAN_CH, 0, s2>>>();              // 2
    scan3_kernel<<<SCAN_NBLK, SCAN_CH, 0, s2>>>();              // 3

    dim3 ggrid(2 * D_OUT / GBN, (N_NODES + GBM - 1) / GBM);     // (4, 782)
    gemm_fp16_kernel<<<ggrid, 256>>>(x, W_l, b_l, W_r, b_r);    // 4 <- ncu slot

    scatter_kernel<<<(N_EDGES + 255) / 256, 256, 0, s2>>>(ei);  // 5

    cudaEventRecord(evJoin, s2);
    cudaStreamWaitEvent(0, evJoin, 0);

    fused_node_kernel<<<N_NODES, 32>>>(att, bias, out);         // 6
}

// round 16
// speedup vs baseline: 2.4416x; 1.3438x over previous
#include <cuda_runtime.h>
#include <cuda_fp16.h>
#include <cstdint>

#define N_NODES 100000
#define N_EDGES 1600000
#define D_IN    480
#define D_OUT   256
#define NEG_SLOPE 0.2f

// ---------------- scratch ----------------
__device__ unsigned g_xl_h[(size_t)N_NODES * (D_OUT / 2)];
__device__ unsigned g_xr_h[(size_t)N_NODES * (D_OUT / 2)];
__device__ int      g_counts[N_NODES];
__device__ int      g_offs[N_NODES];
__device__ int      g_wpos[N_NODES];
__device__ int      g_csrc[N_EDGES];
__device__ int      g_bsum[128];
// fp16 W image in EXACT smem layout: [w][it][n][kp] rows 80B (16 data uints + 4 pad)
__device__ unsigned g_wh[2 * 15 * 256 * 20];

__device__ __forceinline__ unsigned pack_half2(float lo, float hi) {
    unsigned r;
    asm("cvt.rn.f16x2.f32 %0, %1, %2;" : "=r"(r) : "f"(hi), "f"(lo));
    return r;
}
__device__ __forceinline__ float2 h2f2(unsigned u) {
    __half2 h = *reinterpret_cast<__half2*>(&u);
    return __half22float2(h);
}
__device__ __forceinline__ void cvt8(uint4 u, float* x) {
    float2 f;
    f = h2f2(u.x); x[0] = f.x; x[1] = f.y;
    f = h2f2(u.y); x[2] = f.x; x[3] = f.y;
    f = h2f2(u.z); x[4] = f.x; x[5] = f.y;
    f = h2f2(u.w); x[6] = f.x; x[7] = f.y;
}
__device__ __forceinline__ void ldsm_x4(unsigned& r0, unsigned& r1,
                                        unsigned& r2, unsigned& r3, unsigned addr) {
    asm volatile("ldmatrix.sync.aligned.m8n8.x4.shared.b16 {%0,%1,%2,%3}, [%4];"
                 : "=r"(r0), "=r"(r1), "=r"(r2), "=r"(r3) : "r"(addr));
}
#define CP_ASYNC16(sa, gp) \
    asm volatile("cp.async.cg.shared.global [%0], [%1], 16;" :: "r"(sa), "l"(gp) : "memory")
#define CP_COMMIT() asm volatile("cp.async.commit_group;" ::: "memory")
#define CP_WAIT0()  asm volatile("cp.async.wait_group 0;" ::: "memory")

// ---------------- W pre-convert into smem-image layout ----------------
__global__ void wprep_kernel(const float* __restrict__ W_l, const float* __restrict__ W_r) {
    int idx = blockIdx.x * blockDim.x + threadIdx.x;   // 122880
    if (idx >= 2 * 15 * 256 * 16) return;
    int w  = idx / 61440;
    int r  = idx % 61440;
    int it = r / 4096;
    int r2 = r % 4096;
    int n  = r2 >> 4;
    int kp = r2 & 15;
    const float* W = w ? W_r : W_l;
    int k0 = it * 32 + 2 * kp;
    float lo = W[(size_t)k0 * D_OUT + n];
    float hi = W[(size_t)(k0 + 1) * D_OUT + n];
    g_wh[((w * 15 + it) * 256 + n) * 20 + kp] = pack_half2(lo, hi);
}

// ---------------- dst histogram ----------------
__global__ void hist_kernel(const int* __restrict__ ei) {
    int e = blockIdx.x * blockDim.x + threadIdx.x;
    if (e < N_EDGES) atomicAdd(&g_counts[ei[N_EDGES + e]], 1);
}

// ---------------- GEMM: 128x256 CTA, 8 warps of 64x64, fp16 mma + ldmatrix + cp.async B ----------------
#define NIT 15
#define SRB 80
#define A_STG (128 * SRB)     // 10240
#define B_STG (256 * SRB)     // 20480
#define GEMM_SMEM (2 * A_STG + 2 * B_STG)   // 61440

__global__ __launch_bounds__(256, 1)
void gemm_fp16_kernel(const float* __restrict__ X,
                      const float* __restrict__ b_l, const float* __restrict__ b_r) {
    extern __shared__ __align__(16) char sm[];
    unsigned smb;
    { uint64_t t; asm("cvta.to.shared.u64 %0, %1;" : "=l"(t) : "l"(sm)); smb = (unsigned)t; }
    unsigned smb_a = smb;
    unsigned smb_b = smb + 2 * A_STG;

    int tx   = threadIdx.x;
    int lane = tx & 31;
    int wid  = tx >> 5;
    int warp_m = wid & 1;       // 0..1 (64-row halves)
    int warp_n = wid >> 1;      // 0..3 (64-col quarters)
    int gid = lane >> 2;
    int tg  = lane & 3;
    int lrow = lane & 15;
    int lchk = lane >> 4;

    int row0 = blockIdx.y * 128;

    const float* bv; unsigned* Yh; const unsigned* wsrc;
    if (blockIdx.x == 0) { bv = b_l; Yh = g_xl_h; wsrc = g_wh; }
    else                 { bv = b_r; Yh = g_xr_h; wsrc = g_wh + 15 * 5120; }

    int am  = tx >> 3;      // 0..31 (+32 per i)
    int akq = tx & 7;

    float4 ra[4];
    auto loadA = [&](int it) {
#pragma unroll
        for (int i = 0; i < 4; i++) {
            int m  = am + i * 32;
            int gr = row0 + m;
            float4 v = make_float4(0.f, 0.f, 0.f, 0.f);
            if (gr < N_NODES)
                v = *reinterpret_cast<const float4*>(X + (size_t)gr * D_IN + it * 32 + akq * 4);
            ra[i] = v;
        }
    };
    auto storeA = [&](int s) {
        char* Ab = sm + s * A_STG;
#pragma unroll
        for (int i = 0; i < 4; i++) {
            int m = am + i * 32;
            float4 v = ra[i];
            uint2 p = make_uint2(pack_half2(v.x, v.y), pack_half2(v.z, v.w));
            *reinterpret_cast<uint2*>(Ab + m * SRB + akq * 8) = p;
        }
    };
    auto cpB = [&](int it, int s) {
        const uint4* src = reinterpret_cast<const uint4*>(wsrc + it * 5120);
        unsigned dst = smb_b + s * B_STG;
#pragma unroll
        for (int i = 0; i < 5; i++) {
            int idx = tx + i * 256;
            CP_ASYNC16(dst + idx * 16, src + idx);
        }
        CP_COMMIT();
    };

    float acc[4][8][4];
#pragma unroll
    for (int mt = 0; mt < 4; mt++)
#pragma unroll
        for (int nt = 0; nt < 8; nt++)
#pragma unroll
            for (int i = 0; i < 4; i++) acc[mt][nt][i] = 0.f;

    // prologue
    cpB(0, 0);
    loadA(0);
    storeA(0);
    CP_WAIT0();
    __syncthreads();

    for (int it = 0; it < NIT; it++) {
        int cur = it & 1;
        if (it + 1 < NIT) {
            cpB(it + 1, (it + 1) & 1);
            loadA(it + 1);
        }

        unsigned aA = smb_a + cur * A_STG;
        unsigned aB = smb_b + cur * B_STG;
#pragma unroll
        for (int ks = 0; ks < 2; ks++) {
            int kc0 = ks * 2;
            unsigned a[4][4];
#pragma unroll
            for (int mt = 0; mt < 4; mt++) {
                unsigned addr = aA + (warp_m * 64 + mt * 16 + lrow) * SRB + (kc0 + lchk) * 16;
                ldsm_x4(a[mt][0], a[mt][1], a[mt][2], a[mt][3], addr);
            }
            unsigned br[4][4];
#pragma unroll
            for (int pr = 0; pr < 4; pr++) {
                unsigned addr = aB + (warp_n * 64 + pr * 16 + lrow) * SRB + (kc0 + lchk) * 16;
                ldsm_x4(br[pr][0], br[pr][1], br[pr][2], br[pr][3], addr);
            }
#pragma unroll
            for (int pr = 0; pr < 4; pr++) {
#pragma unroll
                for (int sub = 0; sub < 2; sub++) {
                    int nt = pr * 2 + sub;
                    unsigned b0 = br[pr][sub];
                    unsigned b1 = br[pr][sub + 2];
#pragma unroll
                    for (int mt = 0; mt < 4; mt++) {
                        asm volatile(
                            "mma.sync.aligned.m16n8k16.row.col.f32.f16.f16.f32 "
                            "{%0,%1,%2,%3}, {%4,%5,%6,%7}, {%8,%9}, {%0,%1,%2,%3};"
                            : "+f"(acc[mt][nt][0]), "+f"(acc[mt][nt][1]),
                              "+f"(acc[mt][nt][2]), "+f"(acc[mt][nt][3])
                            : "r"(a[mt][0]), "r"(a[mt][1]), "r"(a[mt][2]), "r"(a[mt][3]),
                              "r"(b0), "r"(b1));
                    }
                }
            }
        }

        if (it + 1 < NIT) storeA((it + 1) & 1);
        CP_WAIT0();
        __syncthreads();
    }

#pragma unroll
    for (int mt = 0; mt < 4; mt++) {
        int r = row0 + warp_m * 64 + mt * 16 + gid;
#pragma unroll
        for (int nt = 0; nt < 8; nt++) {
            int c = warp_n * 64 + nt * 8 + tg * 2;
            if (r < N_NODES) {
                Yh[(size_t)r * 128 + (c >> 1)] =
                    pack_half2(acc[mt][nt][0] + bv[c], acc[mt][nt][1] + bv[c + 1]);
            }
            if (r + 8 < N_NODES) {
                Yh[(size_t)(r + 8) * 128 + (c >> 1)] =
                    pack_half2(acc[mt][nt][2] + bv[c], acc[mt][nt][3] + bv[c + 1]);
            }
        }
    }
}

// ---------------- exclusive scan ----------------
#define SCAN_CH 1024
#define SCAN_NBLK ((N_NODES + SCAN_CH - 1) / SCAN_CH)   // 98

__global__ void scan1_kernel() {
    __shared__ int sh[SCAN_CH];
    int t = threadIdx.x;
    int g = blockIdx.x * SCAN_CH + t;
    int v = (g < N_NODES) ? g_counts[g] : 0;
    sh[t] = v;
    __syncthreads();
    for (int o = 1; o < SCAN_CH; o <<= 1) {
        int x = (t >= o) ? sh[t - o] : 0;
        __syncthreads();
        sh[t] += x;
        __syncthreads();
    }
    if (g < N_NODES) g_offs[g] = sh[t] - v;
    if (t == SCAN_CH - 1) g_bsum[blockIdx.x] = sh[t];
}

__global__ void scan3_kernel() {
    __shared__ int sb[128];
    int t = threadIdx.x;
    if (t < 128) sb[t] = (t < blockIdx.x && t < SCAN_NBLK) ? g_bsum[t] : 0;
    __syncthreads();
    if (t < 64) sb[t] += sb[t + 64];
    __syncthreads();
    if (t < 32) {
        int v = sb[t] + sb[t + 32];
#pragma unroll
        for (int o = 16; o > 0; o >>= 1) v += __shfl_xor_sync(0xffffffffu, v, o);
        if (t == 0) sb[0] = v;
    }
    __syncthreads();
    int base = sb[0];
    int g = blockIdx.x * SCAN_CH + t;
    if (g < N_NODES) {
        int v = g_offs[g] + base;
        g_offs[g] = v;
        g_wpos[g] = v;
    }
}

// ---------------- CSR scatter ----------------
__global__ void scatter_kernel(const int* __restrict__ ei) {
    int e = blockIdx.x * blockDim.x + threadIdx.x;
    if (e >= N_EDGES) return;
    int s = __ldg(&ei[e]);
    int d = __ldg(&ei[N_EDGES + e]);
    int pos = atomicAdd(&g_wpos[d], 1);
    g_csrc[pos] = s;
}

// ---------------- fused logits+softmax+aggregate (one warp-block per node) ----------------
__global__ __launch_bounds__(32, 32)
void fused_node_kernel(const float* __restrict__ att,
                       const float* __restrict__ bias,
                       float* __restrict__ out) {
    int node = blockIdx.x;
    int lane = threadIdx.x;
    int beg = g_offs[node];
    int cnt = g_counts[node];

    float xr[8], at[8];
    cvt8(*reinterpret_cast<const uint4*>(g_xr_h + (size_t)node * 128 + lane * 4), xr);
    { const float4* atp = reinterpret_cast<const float4*>(att);
      float4 a0 = atp[lane * 2], a1 = atp[lane * 2 + 1];
      at[0] = a0.x; at[1] = a0.y; at[2] = a0.z; at[3] = a0.w;
      at[4] = a1.x; at[5] = a1.y; at[6] = a1.z; at[7] = a1.w; }

    float acc[8];
#pragma unroll
    for (int i = 0; i < 8; i++) acc[i] = 0.f;
    float denom = 0.f;

    int s_reg = (lane < cnt) ? g_csrc[beg + lane] : 0;
    int batch = 0;

    int j = 0;
    for (; j + 2 <= cnt; j += 2) {
        if ((j >> 5) != batch) {
            batch = j >> 5;
            int idx = beg + batch * 32 + lane;
            s_reg = (batch * 32 + lane < cnt) ? g_csrc[idx] : 0;
        }
        int s0 = __shfl_sync(0xffffffffu, s_reg, j & 31);
        int s1;
        if (((j + 1) >> 5) != batch) {
            batch = (j + 1) >> 5;
            int idx = beg + batch * 32 + lane;
            s_reg = (batch * 32 + lane < cnt) ? g_csrc[idx] : 0;
            s1 = __shfl_sync(0xffffffffu, s_reg, (j + 1) & 31);
        } else {
            s1 = __shfl_sync(0xffffffffu, s_reg, (j + 1) & 31);
        }

        uint4 u0 = *reinterpret_cast<const uint4*>(g_xl_h + (size_t)s0 * 128 + lane * 4);
        uint4 u1 = *reinterpret_cast<const uint4*>(g_xl_h + (size_t)s1 * 128 + lane * 4);

        float x0[8], x1[8];
        cvt8(u0, x0); cvt8(u1, x1);

        float p0 = 0.f, p1 = 0.f;
#pragma unroll
        for (int i = 0; i < 8; i++) {
            float h0 = x0[i] + xr[i]; h0 = h0 > 0.f ? h0 : NEG_SLOPE * h0;
            float h1 = x1[i] + xr[i]; h1 = h1 > 0.f ? h1 : NEG_SLOPE * h1;
            p0 = fmaf(at[i], h0, p0);
            p1 = fmaf(at[i], h1, p1);
        }
#pragma unroll
        for (int o = 16; o > 0; o >>= 1) {
            p0 += __shfl_xor_sync(0xffffffffu, p0, o);
            p1 += __shfl_xor_sync(0xffffffffu, p1, o);
        }
        float w0 = __expf(p0);
        float w1 = __expf(p1);
        denom += w0 + w1;
#pragma unroll
        for (int i = 0; i < 8; i++) {
            float t = fmaf(w0, x0[i], acc[i]);
            acc[i]  = fmaf(w1, x1[i], t);
        }
    }
    if (j < cnt) {
        if ((j >> 5) != batch) {
            batch = j >> 5;
            int idx = beg + batch * 32 + lane;
            s_reg = (batch * 32 + lane < cnt) ? g_csrc[idx] : 0;
        }
        int s0 = __shfl_sync(0xffffffffu, s_reg, j & 31);
        uint4 u0 = *reinterpret_cast<const uint4*>(g_xl_h + (size_t)s0 * 128 + lane * 4);
        float x0[8];
        cvt8(u0, x0);
        float p0 = 0.f;
#pragma unroll
        for (int i = 0; i < 8; i++) {
            float h0 = x0[i] + xr[i]; h0 = h0 > 0.f ? h0 : NEG_SLOPE * h0;
            p0 = fmaf(at[i], h0, p0);
        }
#pragma unroll
        for (int o = 16; o > 0; o >>= 1) p0 += __shfl_xor_sync(0xffffffffu, p0, o);
        float w0 = __expf(p0);
        denom += w0;
#pragma unroll
        for (int i = 0; i < 8; i++) acc[i] = fmaf(w0, x0[i], acc[i]);
    }

    float rd = 1.f / (denom + 1e-16f);
    const float4* bi = reinterpret_cast<const float4*>(bias);
    float4 bb0 = bi[lane * 2], bb1 = bi[lane * 2 + 1];
    float4 o0 = make_float4(fmaf(acc[0], rd, bb0.x), fmaf(acc[1], rd, bb0.y),
                            fmaf(acc[2], rd, bb0.z), fmaf(acc[3], rd, bb0.w));
    float4 o1 = make_float4(fmaf(acc[4], rd, bb1.x), fmaf(acc[5], rd, bb1.y),
                            fmaf(acc[6], rd, bb1.z), fmaf(acc[7], rd, bb1.w));
    float4* op = reinterpret_cast<float4*>(out + (size_t)node * D_OUT + lane * 8);
    op[0] = o0;
    op[1] = o1;
}

// ---------------- launch (forked capture: CSR chain || wprep+GEMM) ----------------
extern "C" void kernel_launch(void* const* d_in, const int* in_sizes, int n_in,
                              void* d_out, int out_size) {
    const float* x    = (const float*)d_in[0];
    const int*   ei   = (const int*)d_in[1];
    const float* W_l  = (const float*)d_in[2];
    const float* b_l  = (const float*)d_in[3];
    const float* W_r  = (const float*)d_in[4];
    const float* b_r  = (const float*)d_in[5];
    const float* att  = (const float*)d_in[6];
    const float* bias = (const float*)d_in[7];
    float* out = (float*)d_out;

    static cudaStream_t s2 = nullptr;
    static cudaEvent_t evFork = nullptr, evJoin = nullptr;
    static int* counts_ptr = nullptr;
    if (s2 == nullptr) {
        cudaStreamCreateWithFlags(&s2, cudaStreamNonBlocking);
        cudaEventCreateWithFlags(&evFork, cudaEventDisableTiming);
        cudaEventCreateWithFlags(&evJoin, cudaEventDisableTiming);
        cudaGetSymbolAddress((void**)&counts_ptr, g_counts);
        cudaFuncSetAttribute(gemm_fp16_kernel,
                             cudaFuncAttributeMaxDynamicSharedMemorySize, GEMM_SMEM);
    }

    cudaEventRecord(evFork, 0);
    cudaStreamWaitEvent(s2, evFork, 0);

    wprep_kernel<<<480, 256>>>(W_l, W_r);                       // 1 (default stream)
    cudaMemsetAsync(counts_ptr, 0, N_NODES * sizeof(int), s2);
    hist_kernel<<<(N_EDGES + 255) / 256, 256, 0, s2>>>(ei);     // 2
    scan1_kernel<<<SCAN_NBLK, SCAN_CH, 0, s2>>>();              // 3

    dim3 ggrid(2, (N_NODES + 127) / 128);                       // (2, 782)
    gemm_fp16_kernel<<<ggrid, 256, GEMM_SMEM>>>(x, b_l, b_r);   // 4 <- ncu slot

    scan3_kernel<<<SCAN_NBLK, SCAN_CH, 0, s2>>>();              // 5
    scatter_kernel<<<(N_EDGES + 255) / 256, 256, 0, s2>>>(ei);  // 6

    cudaEventRecord(evJoin, s2);
    cudaStreamWaitEvent(0, evJoin, 0);

    fused_node_kernel<<<N_NODES, 32>>>(att, bias, out);         // 7
}

// round 17
// speedup vs baseline: 2.5094x; 1.0278x over previous
#include <cuda_runtime.h>
#include <cuda_fp16.h>
#include <cstdint>

#define N_NODES 100000
#define N_EDGES 1600000
#define D_IN    480
#define D_OUT   256
#define NEG_SLOPE 0.2f

// ---------------- scratch ----------------
__device__ unsigned g_xl_h[(size_t)N_NODES * (D_OUT / 2)];
__device__ unsigned g_xr_h[(size_t)N_NODES * (D_OUT / 2)];
__device__ int      g_counts[N_NODES];
__device__ int      g_offs[N_NODES];
__device__ int      g_wpos[N_NODES];
__device__ int      g_csrc[N_EDGES];
__device__ int      g_bsum[128];
// fp16 W image in EXACT smem layout: [w][it][n][kp] rows 80B (16 data uints + 4 pad)
__device__ unsigned g_wh[2 * 15 * 256 * 20];

__device__ __forceinline__ unsigned pack_half2(float lo, float hi) {
    unsigned r;
    asm("cvt.rn.f16x2.f32 %0, %1, %2;" : "=r"(r) : "f"(hi), "f"(lo));
    return r;
}
__device__ __forceinline__ float2 h2f2(unsigned u) {
    __half2 h = *reinterpret_cast<__half2*>(&u);
    return __half22float2(h);
}
__device__ __forceinline__ void cvt8(uint4 u, float* x) {
    float2 f;
    f = h2f2(u.x); x[0] = f.x; x[1] = f.y;
    f = h2f2(u.y); x[2] = f.x; x[3] = f.y;
    f = h2f2(u.z); x[4] = f.x; x[5] = f.y;
    f = h2f2(u.w); x[6] = f.x; x[7] = f.y;
}
__device__ __forceinline__ void ldsm_x4(unsigned& r0, unsigned& r1,
                                        unsigned& r2, unsigned& r3, unsigned addr) {
    asm volatile("ldmatrix.sync.aligned.m8n8.x4.shared.b16 {%0,%1,%2,%3}, [%4];"
                 : "=r"(r0), "=r"(r1), "=r"(r2), "=r"(r3) : "r"(addr));
}
#define CP_ASYNC16(sa, gp) \
    asm volatile("cp.async.cg.shared.global [%0], [%1], 16;" :: "r"(sa), "l"(gp) : "memory")
#define CP_COMMIT() asm volatile("cp.async.commit_group;" ::: "memory")
#define CP_WAIT0()  asm volatile("cp.async.wait_group 0;" ::: "memory")

// ---------------- W pre-convert into smem-image layout ----------------
__global__ void wprep_kernel(const float* __restrict__ W_l, const float* __restrict__ W_r) {
    int idx = blockIdx.x * blockDim.x + threadIdx.x;   // 122880
    if (idx >= 2 * 15 * 256 * 16) return;
    int w  = idx / 61440;
    int r  = idx % 61440;
    int it = r / 4096;
    int r2 = r % 4096;
    int n  = r2 >> 4;
    int kp = r2 & 15;
    const float* W = w ? W_r : W_l;
    int k0 = it * 32 + 2 * kp;
    float lo = W[(size_t)k0 * D_OUT + n];
    float hi = W[(size_t)(k0 + 1) * D_OUT + n];
    g_wh[((w * 15 + it) * 256 + n) * 20 + kp] = pack_half2(lo, hi);
}

// ---------------- dst histogram ----------------
__global__ void hist_kernel(const int* __restrict__ ei) {
    int e = blockIdx.x * blockDim.x + threadIdx.x;
    if (e < N_EDGES) atomicAdd(&g_counts[ei[N_EDGES + e]], 1);
}

// ---------------- GEMM: 128x128 CTA (128 thr, 4 warps of 64x64), 2 CTAs/SM ----------------
#define NIT 15
#define SRB 80
#define A_STG (128 * SRB)     // 10240
#define B_STG (128 * SRB)     // 10240
#define GEMM_SMEM (2 * A_STG + 2 * B_STG)   // 40960

__global__ __launch_bounds__(128, 2)
void gemm_fp16_kernel(const float* __restrict__ X,
                      const float* __restrict__ b_l, const float* __restrict__ b_r) {
    extern __shared__ __align__(16) char sm[];
    unsigned smb;
    { uint64_t t; asm("cvta.to.shared.u64 %0, %1;" : "=l"(t) : "l"(sm)); smb = (unsigned)t; }
    unsigned smb_a = smb;
    unsigned smb_b = smb + 2 * A_STG;

    int tx   = threadIdx.x;
    int lane = tx & 31;
    int wid  = tx >> 5;         // 0..3
    int warp_m = wid & 1;       // 0..1 (64-row halves)
    int warp_n = wid >> 1;      // 0..1 (64-col halves)
    int gid = lane >> 2;
    int tg  = lane & 3;
    int lrow = lane & 15;
    int lchk = lane >> 4;

    int row0 = blockIdx.y * 128;
    int w  = blockIdx.x >> 1;   // 0=W_l, 1=W_r
    int ch = blockIdx.x & 1;    // column half
    int col0 = ch * 128;

    const float* bv = w ? b_r : b_l;
    unsigned* Yh    = w ? g_xr_h : g_xl_h;
    const unsigned* wsrc = g_wh + w * (15 * 5120) + col0 * 20;

    // A loader: 8 float4/thread (128 thr): f = tx + i*128 -> m = f>>3, q = f&7
    int am  = tx >> 3;      // 0..15 (+16 per i)
    int akq = tx & 7;

    float4 ra[8];
    auto loadA = [&](int it) {
#pragma unroll
        for (int i = 0; i < 8; i++) {
            int m  = am + i * 16;
            int gr = row0 + m;
            float4 v = make_float4(0.f, 0.f, 0.f, 0.f);
            if (gr < N_NODES)
                v = *reinterpret_cast<const float4*>(X + (size_t)gr * D_IN + it * 32 + akq * 4);
            ra[i] = v;
        }
    };
    auto storeA = [&](int s) {
        char* Ab = sm + s * A_STG;
#pragma unroll
        for (int i = 0; i < 8; i++) {
            int m = am + i * 16;
            float4 v = ra[i];
            uint2 p = make_uint2(pack_half2(v.x, v.y), pack_half2(v.z, v.w));
            *reinterpret_cast<uint2*>(Ab + m * SRB + akq * 8) = p;
        }
    };
    auto cpB = [&](int it, int s) {
        // 128 rows x 80B = 10240B = 640 uint4; 5 per thread
        const uint4* src = reinterpret_cast<const uint4*>(wsrc + it * 5120);
        unsigned dst = smb_b + s * B_STG;
#pragma unroll
        for (int i = 0; i < 5; i++) {
            int idx = tx + i * 128;
            CP_ASYNC16(dst + idx * 16, src + idx);
        }
        CP_COMMIT();
    };

    float acc[4][8][4];
#pragma unroll
    for (int mt = 0; mt < 4; mt++)
#pragma unroll
        for (int nt = 0; nt < 8; nt++)
#pragma unroll
            for (int i = 0; i < 4; i++) acc[mt][nt][i] = 0.f;

    // prologue
    cpB(0, 0);
    loadA(0);
    storeA(0);
    CP_WAIT0();
    __syncthreads();

    for (int it = 0; it < NIT; it++) {
        int cur = it & 1;
        if (it + 1 < NIT) {
            cpB(it + 1, (it + 1) & 1);
            loadA(it + 1);
        }

        unsigned aA = smb_a + cur * A_STG;
        unsigned aB = smb_b + cur * B_STG;
#pragma unroll
        for (int ks = 0; ks < 2; ks++) {
            int kc0 = ks * 2;
            unsigned a[4][4];
#pragma unroll
            for (int mt = 0; mt < 4; mt++) {
                unsigned addr = aA + (warp_m * 64 + mt * 16 + lrow) * SRB + (kc0 + lchk) * 16;
                ldsm_x4(a[mt][0], a[mt][1], a[mt][2], a[mt][3], addr);
            }
            unsigned br[4][4];
#pragma unroll
            for (int pr = 0; pr < 4; pr++) {
                unsigned addr = aB + (warp_n * 64 + pr * 16 + lrow) * SRB + (kc0 + lchk) * 16;
                ldsm_x4(br[pr][0], br[pr][1], br[pr][2], br[pr][3], addr);
            }
#pragma unroll
            for (int pr = 0; pr < 4; pr++) {
#pragma unroll
                for (int sub = 0; sub < 2; sub++) {
                    int nt = pr * 2 + sub;
                    unsigned b0 = br[pr][sub];
                    unsigned b1 = br[pr][sub + 2];
#pragma unroll
                    for (int mt = 0; mt < 4; mt++) {
                        asm volatile(
                            "mma.sync.aligned.m16n8k16.row.col.f32.f16.f16.f32 "
                            "{%0,%1,%2,%3}, {%4,%5,%6,%7}, {%8,%9}, {%0,%1,%2,%3};"
                            : "+f"(acc[mt][nt][0]), "+f"(acc[mt][nt][1]),
                              "+f"(acc[mt][nt][2]), "+f"(acc[mt][nt][3])
                            : "r"(a[mt][0]), "r"(a[mt][1]), "r"(a[mt][2]), "r"(a[mt][3]),
                              "r"(b0), "r"(b1));
                    }
                }
            }
        }

        if (it + 1 < NIT) storeA((it + 1) & 1);
        CP_WAIT0();
        __syncthreads();
    }

#pragma unroll
    for (int mt = 0; mt < 4; mt++) {
        int r = row0 + warp_m * 64 + mt * 16 + gid;
#pragma unroll
        for (int nt = 0; nt < 8; nt++) {
            int c = col0 + warp_n * 64 + nt * 8 + tg * 2;
            if (r < N_NODES) {
                Yh[(size_t)r * 128 + (c >> 1)] =
                    pack_half2(acc[mt][nt][0] + bv[c], acc[mt][nt][1] + bv[c + 1]);
            }
            if (r + 8 < N_NODES) {
                Yh[(size_t)(r + 8) * 128 + (c >> 1)] =
                    pack_half2(acc[mt][nt][2] + bv[c], acc[mt][nt][3] + bv[c + 1]);
            }
        }
    }
}

// ---------------- exclusive scan ----------------
#define SCAN_CH 1024
#define SCAN_NBLK ((N_NODES + SCAN_CH - 1) / SCAN_CH)   // 98

__global__ void scan1_kernel() {
    __shared__ int sh[SCAN_CH];
    int t = threadIdx.x;
    int g = blockIdx.x * SCAN_CH + t;
    int v = (g < N_NODES) ? g_counts[g] : 0;
    sh[t] = v;
    __syncthreads();
    for (int o = 1; o < SCAN_CH; o <<= 1) {
        int x = (t >= o) ? sh[t - o] : 0;
        __syncthreads();
        sh[t] += x;
        __syncthreads();
    }
    if (g < N_NODES) g_offs[g] = sh[t] - v;
    if (t == SCAN_CH - 1) g_bsum[blockIdx.x] = sh[t];
}

__global__ void scan3_kernel() {
    __shared__ int sb[128];
    int t = threadIdx.x;
    if (t < 128) sb[t] = (t < blockIdx.x && t < SCAN_NBLK) ? g_bsum[t] : 0;
    __syncthreads();
    if (t < 64) sb[t] += sb[t + 64];
    __syncthreads();
    if (t < 32) {
        int v = sb[t] + sb[t + 32];
#pragma unroll
        for (int o = 16; o > 0; o >>= 1) v += __shfl_xor_sync(0xffffffffu, v, o);
        if (t == 0) sb[0] = v;
    }
    __syncthreads();
    int base = sb[0];
    int g = blockIdx.x * SCAN_CH + t;
    if (g < N_NODES) {
        int v = g_offs[g] + base;
        g_offs[g] = v;
        g_wpos[g] = v;
    }
}

// ---------------- CSR scatter ----------------
__global__ void scatter_kernel(const int* __restrict__ ei) {
    int e = blockIdx.x * blockDim.x + threadIdx.x;
    if (e >= N_EDGES) return;
    int s = __ldg(&ei[e]);
    int d = __ldg(&ei[N_EDGES + e]);
    int pos = atomicAdd(&g_wpos[d], 1);
    g_csrc[pos] = s;
}

// ---------------- fused logits+softmax+aggregate (one warp-block per node) ----------------
__global__ __launch_bounds__(32, 32)
void fused_node_kernel(const float* __restrict__ att,
                       const float* __restrict__ bias,
                       float* __restrict__ out) {
    int node = blockIdx.x;
    int lane = threadIdx.x;
    int beg = g_offs[node];
    int cnt = g_counts[node];

    float xr[8], at[8];
    cvt8(*reinterpret_cast<const uint4*>(g_xr_h + (size_t)node * 128 + lane * 4), xr);
    { const float4* atp = reinterpret_cast<const float4*>(att);
      float4 a0 = atp[lane * 2], a1 = atp[lane * 2 + 1];
      at[0] = a0.x; at[1] = a0.y; at[2] = a0.z; at[3] = a0.w;
      at[4] = a1.x; at[5] = a1.y; at[6] = a1.z; at[7] = a1.w; }

    float acc[8];
#pragma unroll
    for (int i = 0; i < 8; i++) acc[i] = 0.f;
    float denom = 0.f;

    int s_reg = (lane < cnt) ? g_csrc[beg + lane] : 0;
    int batch = 0;

    int j = 0;
    for (; j + 2 <= cnt; j += 2) {
        if ((j >> 5) != batch) {
            batch = j >> 5;
            int idx = beg + batch * 32 + lane;
            s_reg = (batch * 32 + lane < cnt) ? g_csrc[idx] : 0;
        }
        int s0 = __shfl_sync(0xffffffffu, s_reg, j & 31);
        int s1;
        if (((j + 1) >> 5) != batch) {
            batch = (j + 1) >> 5;
            int idx = beg + batch * 32 + lane;
            s_reg = (batch * 32 + lane < cnt) ? g_csrc[idx] : 0;
            s1 = __shfl_sync(0xffffffffu, s_reg, (j + 1) & 31);
        } else {
            s1 = __shfl_sync(0xffffffffu, s_reg, (j + 1) & 31);
        }

        uint4 u0 = *reinterpret_cast<const uint4*>(g_xl_h + (size_t)s0 * 128 + lane * 4);
        uint4 u1 = *reinterpret_cast<const uint4*>(g_xl_h + (size_t)s1 * 128 + lane * 4);

        float x0[8], x1[8];
        cvt8(u0, x0); cvt8(u1, x1);

        float p0 = 0.f, p1 = 0.f;
#pragma unroll
        for (int i = 0; i < 8; i++) {
            float h0 = x0[i] + xr[i]; h0 = h0 > 0.f ? h0 : NEG_SLOPE * h0;
            float h1 = x1[i] + xr[i]; h1 = h1 > 0.f ? h1 : NEG_SLOPE * h1;
            p0 = fmaf(at[i], h0, p0);
            p1 = fmaf(at[i], h1, p1);
        }
#pragma unroll
        for (int o = 16; o > 0; o >>= 1) {
            p0 += __shfl_xor_sync(0xffffffffu, p0, o);
            p1 += __shfl_xor_sync(0xffffffffu, p1, o);
        }
        float w0 = __expf(p0);
        float w1 = __expf(p1);
        denom += w0 + w1;
#pragma unroll
        for (int i = 0; i < 8; i++) {
            float t = fmaf(w0, x0[i], acc[i]);
            acc[i]  = fmaf(w1, x1[i], t);
        }
    }
    if (j < cnt) {
        if ((j >> 5) != batch) {
            batch = j >> 5;
            int idx = beg + batch * 32 + lane;
            s_reg = (batch * 32 + lane < cnt) ? g_csrc[idx] : 0;
        }
        int s0 = __shfl_sync(0xffffffffu, s_reg, j & 31);
        uint4 u0 = *reinterpret_cast<const uint4*>(g_xl_h + (size_t)s0 * 128 + lane * 4);
        float x0[8];
        cvt8(u0, x0);
        float p0 = 0.f;
#pragma unroll
        for (int i = 0; i < 8; i++) {
            float h0 = x0[i] + xr[i]; h0 = h0 > 0.f ? h0 : NEG_SLOPE * h0;
            p0 = fmaf(at[i], h0, p0);
        }
#pragma unroll
        for (int o = 16; o > 0; o >>= 1) p0 += __shfl_xor_sync(0xffffffffu, p0, o);
        float w0 = __expf(p0);
        denom += w0;
#pragma unroll
        for (int i = 0; i < 8; i++) acc[i] = fmaf(w0, x0[i], acc[i]);
    }

    float rd = 1.f / (denom + 1e-16f);
    const float4* bi = reinterpret_cast<const float4*>(bias);
    float4 bb0 = bi[lane * 2], bb1 = bi[lane * 2 + 1];
    float4 o0 = make_float4(fmaf(acc[0], rd, bb0.x), fmaf(acc[1], rd, bb0.y),
                            fmaf(acc[2], rd, bb0.z), fmaf(acc[3], rd, bb0.w));
    float4 o1 = make_float4(fmaf(acc[4], rd, bb1.x), fmaf(acc[5], rd, bb1.y),
                            fmaf(acc[6], rd, bb1.z), fmaf(acc[7], rd, bb1.w));
    float4* op = reinterpret_cast<float4*>(out + (size_t)node * D_OUT + lane * 8);
    op[0] = o0;
    op[1] = o1;
}

// ---------------- launch (forked capture: CSR chain || wprep+GEMM) ----------------
extern "C" void kernel_launch(void* const* d_in, const int* in_sizes, int n_in,
                              void* d_out, int out_size) {
    const float* x    = (const float*)d_in[0];
    const int*   ei   = (const int*)d_in[1];
    const float* W_l  = (const float*)d_in[2];
    const float* b_l  = (const float*)d_in[3];
    const float* W_r  = (const float*)d_in[4];
    const float* b_r  = (const float*)d_in[5];
    const float* att  = (const float*)d_in[6];
    const float* bias = (const float*)d_in[7];
    float* out = (float*)d_out;

    static cudaStream_t s2 = nullptr;
    static cudaEvent_t evFork = nullptr, evJoin = nullptr;
    static int* counts_ptr = nullptr;
    if (s2 == nullptr) {
        cudaStreamCreateWithFlags(&s2, cudaStreamNonBlocking);
        cudaEventCreateWithFlags(&evFork, cudaEventDisableTiming);
        cudaEventCreateWithFlags(&evJoin, cudaEventDisableTiming);
        cudaGetSymbolAddress((void**)&counts_ptr, g_counts);
        cudaFuncSetAttribute(gemm_fp16_kernel,
                             cudaFuncAttributeMaxDynamicSharedMemorySize, GEMM_SMEM);
    }

    cudaEventRecord(evFork, 0);
    cudaStreamWaitEvent(s2, evFork, 0);

    wprep_kernel<<<480, 256>>>(W_l, W_r);                       // 1 (default stream)
    cudaMemsetAsync(counts_ptr, 0, N_NODES * sizeof(int), s2);
    hist_kernel<<<(N_EDGES + 255) / 256, 256, 0, s2>>>(ei);     // 2
    scan1_kernel<<<SCAN_NBLK, SCAN_CH, 0, s2>>>();              // 3

    dim3 ggrid(4, (N_NODES + 127) / 128);                       // (4, 782)
    gemm_fp16_kernel<<<ggrid, 128, GEMM_SMEM>>>(x, b_l, b_r);   // 4 <- ncu slot

    scan3_kernel<<<SCAN_NBLK, SCAN_CH, 0, s2>>>();              // 5
    scatter_kernel<<<(N_EDGES + 255) / 256, 256, 0, s2>>>(ei);  // 6

    cudaEventRecord(evJoin, s2);
    cudaStreamWaitEvent(0, evJoin, 0);

    fused_node_kernel<<<N_NODES, 32>>>(att, bias, out);         // 7
}